// round 1
// baseline (speedup 1.0000x reference)
#include <cuda_runtime.h>

#define BATCH 16
#define ANCH 22743
#define ROW 85
#define NCLS 80
#define NSC (ANCH * NCLS)
#define CAP 16384
#define ALIST_CAP 6144
#define PRE 1000
#define MAXDET 300
#define SORTN 16384
#define CONF_THRESH 0.2f
#define PRE_THRESH 0.9f
#define NMS_THRESH 0.45f
#define MAXK 64

// ---------------- device scratch (no allocations allowed) ----------------
__device__ int g_cnt0[BATCH];
__device__ int g_acnt[BATCH];
__device__ int g_need[BATCH];
__device__ unsigned long long g_cand[BATCH][CAP];
__device__ int g_alist[BATCH][ALIST_CAP];

// ---------------- shared memory layout for final kernel ----------------
// keys: 16384 * 8           = 131072
// raw boxes 4 x 1024 f32    =  16384  -> 131072
// shifted 5 x 1024 f32      =  20480  -> 147456
// scores 1024 f32           =   4096  -> 167936
// labels 1024 i32           =   4096  -> 172032
// clist 80*64 i32           =  20480  -> 176128
// ccnt 128 i32              =    512  -> 196608
// keep 1024 i32             =   4096  -> 197120
// scan 1024 i32             =   4096  -> 201216
// max 1 i32 (+pad)          =     16  -> 205312
#define SM_KEYS 0
#define SM_RB 131072
#define SM_SX 147456
#define SM_SC 167936
#define SM_LB 172032
#define SM_CL 176128
#define SM_CC 196608
#define SM_KP 197120
#define SM_SN 201216
#define SM_MX 205312
#define SMEM_FINAL 205440

__global__ void reset_kernel() {
    int t = threadIdx.x;
    if (t < BATCH) { g_cnt0[t] = 0; g_acnt[t] = 0; g_need[t] = 0; }
}

// Phase A: find anchors whose conf > 0.9 (necessary condition for score > 0.9)
__global__ void conf_kernel(const float* __restrict__ preds) {
    int b = blockIdx.y;
    int a = blockIdx.x * blockDim.x + threadIdx.x;
    bool inb = a < ANCH;
    float conf = inb ? preds[((size_t)b * ANCH + a) * ROW + 4] : 0.0f;
    bool pred = inb && (conf > PRE_THRESH);
    unsigned m = __ballot_sync(0xffffffffu, pred);
    if (pred) {
        int lane = threadIdx.x & 31;
        int leader = __ffs(m) - 1;
        int rank = __popc(m & ((1u << lane) - 1u));
        int basep;
        if (lane == leader) basep = atomicAdd(&g_acnt[b], __popc(m));
        basep = __shfl_sync(m, basep, leader);
        int pos = basep + rank;
        if (pos < ALIST_CAP) g_alist[b][pos] = a;
    }
}

// Phase B: for selected anchors, emit candidates with score > 0.9
__global__ void cand_kernel(const float* __restrict__ preds) {
    int b = blockIdx.y;
    int lane = threadIdx.x & 31;
    int warps_per_grid = gridDim.x * (blockDim.x >> 5);
    int gw = blockIdx.x * (blockDim.x >> 5) + (threadIdx.x >> 5);
    int n = min(g_acnt[b], ALIST_CAP);
    for (int idx = gw; idx < n; idx += warps_per_grid) {
        int a = g_alist[b][idx];
        const float* row = preds + ((size_t)b * ANCH + a) * ROW;
        float conf = row[4];
#pragma unroll
        for (int part = 0; part < 3; part++) {
            int k = part * 32 + lane;
            float p = (k < NCLS) ? row[5 + k] : 0.0f;
            float s = __fmul_rn(p, conf);
            bool pred = (k < NCLS) && (s > PRE_THRESH);
            unsigned m = __ballot_sync(0xffffffffu, pred);
            if (pred) {
                int leader = __ffs(m) - 1;
                int rank = __popc(m & ((1u << lane) - 1u));
                int basep;
                if (lane == leader) basep = atomicAdd(&g_cnt0[b], __popc(m));
                basep = __shfl_sync(m, basep, leader);
                int pos = basep + rank;
                if (pos < CAP) {
                    unsigned flat = (unsigned)a * 80u + (unsigned)k;
                    g_cand[b][pos] =
                        ((unsigned long long)__float_as_uint(s) << 32) |
                        (unsigned long long)(~flat);
                }
            }
        }
    }
}

__global__ void need_kernel() {
    int b = threadIdx.x;
    if (b < BATCH) g_need[b] = (min(g_cnt0[b], CAP) < PRE) ? 1 : 0;
}

// Safety net (normally exits immediately): append scores in (0.2, 0.9]
__global__ void fallback_kernel(const float* __restrict__ preds) {
    int b = blockIdx.y;
    if (g_need[b] == 0) return;
    const float* base = preds + (size_t)b * ANCH * ROW;
    int tid0 = blockIdx.x * blockDim.x + threadIdx.x;
    int stride = gridDim.x * blockDim.x;
    int lane = threadIdx.x & 31;
    const int NRUP = ((NSC + 31) & ~31);
    for (int i = tid0; i < NRUP; i += stride) {
        bool inb = i < NSC;
        float s = 0.0f;
        unsigned flat = (unsigned)i;
        if (inb) {
            unsigned a = flat / 80u;
            unsigned k = flat - a * 80u;
            float conf = base[(size_t)a * ROW + 4];
            float p = base[(size_t)a * ROW + 5 + k];
            s = __fmul_rn(p, conf);
        }
        bool pred = inb && (s > CONF_THRESH) && !(s > PRE_THRESH);
        unsigned m = __ballot_sync(0xffffffffu, pred);
        if (pred) {
            int leader = __ffs(m) - 1;
            int rank = __popc(m & ((1u << lane) - 1u));
            int basep;
            if (lane == leader) basep = atomicAdd(&g_cnt0[b], __popc(m));
            basep = __shfl_sync(m, basep, leader);
            int pos = basep + rank;
            if (pos < CAP)
                g_cand[b][pos] =
                    ((unsigned long long)__float_as_uint(s) << 32) |
                    (unsigned long long)(~flat);
        }
    }
}

// Per-image: sort candidates, take top-1000, per-class greedy NMS, emit top-300
__global__ void __launch_bounds__(1024, 1)
final_kernel(const float* __restrict__ preds, float* __restrict__ out) {
    extern __shared__ char smc[];
    unsigned long long* keys = (unsigned long long*)(smc + SM_KEYS);
    float* rbx1 = (float*)(smc + SM_RB);
    float* rby1 = rbx1 + 1024;
    float* rbx2 = rbx1 + 2048;
    float* rby2 = rbx1 + 3072;
    float* sx1 = (float*)(smc + SM_SX);
    float* sy1 = sx1 + 1024;
    float* sx2 = sx1 + 2048;
    float* sy2 = sx1 + 3072;
    float* sar = sx1 + 4096;
    float* ssc = (float*)(smc + SM_SC);
    int* slb = (int*)(smc + SM_LB);
    int* clist = (int*)(smc + SM_CL);
    int* ccnt = (int*)(smc + SM_CC);
    int* keepf = (int*)(smc + SM_KP);
    int* scan = (int*)(smc + SM_SN);
    int* smax = (int*)(smc + SM_MX);

    int b = blockIdx.x;
    int tid = threadIdx.x;

    int n = min(g_cnt0[b], CAP);
    for (int i = tid; i < SORTN; i += 1024)
        keys[i] = (i < n) ? g_cand[b][i] : 0ull;
    if (tid < 128) ccnt[tid] = 0;
    keepf[tid] = 0;
    if (tid == 0) *smax = 0;
    __syncthreads();

    // Bitonic sort ascending (unique keys; zero padding sinks to the bottom)
    for (int k = 2; k <= SORTN; k <<= 1) {
        for (int j = k >> 1; j > 0; j >>= 1) {
            for (int i = tid; i < SORTN; i += 1024) {
                int ixj = i ^ j;
                if (ixj > i) {
                    unsigned long long va = keys[i], vb = keys[ixj];
                    bool up = ((i & k) == 0);
                    if ((va > vb) == up) { keys[i] = vb; keys[ixj] = va; }
                }
            }
            __syncthreads();
        }
    }

    // Decode top-1000 (descending = from the top of the ascending array)
    {
        int j = tid;
        unsigned long long key = (j < PRE) ? keys[SORTN - 1 - j] : 0ull;
        float sc = -1.0f;
        unsigned flat = 0u;
        if (j < PRE && key != 0ull) {
            sc = __uint_as_float((unsigned)(key >> 32));
            flat = ~((unsigned)(key & 0xffffffffull));
        }
        unsigned a = flat / 80u;
        unsigned lbl = flat - a * 80u;
        if (a >= ANCH) { a = 0; lbl = 0; }
        const float* row = preds + ((size_t)b * ANCH + a) * ROW;
        float b0 = row[0], b1 = row[1], b2 = row[2], b3 = row[3];
        rbx1[j] = b0; rby1[j] = b1; rbx2[j] = b2; rby2[j] = b3;
        ssc[j] = sc;
        slb[j] = (int)lbl;
        if (j < PRE) {
            float mx = fmaxf(fmaxf(b0, b1), fmaxf(b2, b3));
            atomicMax(smax, __float_as_int(mx));  // coords >= 0: int-bits order = float order
        }
    }
    __syncthreads();

    float M = __int_as_float(*smax);
    float shb = __fadd_rn(M, 1.0f);
    {
        int j = tid;
        float sh = __fmul_rn((float)slb[j], shb);
        float x1 = __fadd_rn(rbx1[j], sh);
        float y1 = __fadd_rn(rby1[j], sh);
        float x2 = __fadd_rn(rbx2[j], sh);
        float y2 = __fadd_rn(rby2[j], sh);
        sx1[j] = x1; sy1[j] = y1; sx2[j] = x2; sy2[j] = y2;
        sar[j] = __fmul_rn(fmaxf(__fsub_rn(x2, x1), 0.0f),
                           fmaxf(__fsub_rn(y2, y1), 0.0f));
    }
    __syncthreads();

    // Stable per-class grouping (warp 0, preserves ascending j = descending score)
    if ((tid >> 5) == 0) {
        int lane = tid & 31;
        for (int jb = 0; jb < PRE; jb += 32) {
            int j = jb + lane;
            bool act = j < PRE;
            int lbl = act ? slb[j] : -1;
            unsigned m = __match_any_sync(0xffffffffu, lbl);
            if (act) {
                int leader = __ffs(m) - 1;
                int rank = __popc(m & ((1u << lane) - 1u));
                int basep;
                if (lane == leader) basep = ccnt[lbl];
                basep = __shfl_sync(m, basep, leader);
                int pos = basep + rank;
                if (pos < MAXK) clist[lbl * MAXK + pos] = j;
                if (lane == leader) ccnt[lbl] = basep + __popc(m);
            }
            __syncwarp();
        }
    }
    __syncthreads();

    // Per-class greedy NMS (cross-class shifted IoU is exactly 0 -> classes independent)
    if (tid < NCLS) {
        int c = tid;
        int kc = min(ccnt[c], MAXK);
        unsigned long long keep = 0ull;
        for (int ii = 0; ii < kc; ii++) {
            int j = clist[c * MAXK + ii];
            if (ssc[j] > CONF_THRESH) keep |= (1ull << ii);
        }
        for (int ii = 0; ii < kc; ii++) {
            if (!((keep >> ii) & 1ull)) continue;
            int ji = clist[c * MAXK + ii];
            float ax1 = sx1[ji], ay1 = sy1[ji], ax2 = sx2[ji], ay2 = sy2[ji];
            float aar = sar[ji];
            for (int jj = ii + 1; jj < kc; jj++) {
                if (!((keep >> jj) & 1ull)) continue;
                int j2 = clist[c * MAXK + jj];
                float ix1 = fmaxf(ax1, sx1[j2]);
                float iy1 = fmaxf(ay1, sy1[j2]);
                float ix2 = fminf(ax2, sx2[j2]);
                float iy2 = fminf(ay2, sy2[j2]);
                float iw = fmaxf(__fsub_rn(ix2, ix1), 0.0f);
                float ih = fmaxf(__fsub_rn(iy2, iy1), 0.0f);
                float inter = __fmul_rn(iw, ih);
                float den = __fadd_rn(__fsub_rn(__fadd_rn(aar, sar[j2]), inter), 1e-7f);
                float iou = __fdiv_rn(inter, den);
                if (iou > NMS_THRESH) keep &= ~(1ull << jj);
            }
        }
        for (int ii = 0; ii < kc; ii++)
            keepf[clist[c * MAXK + ii]] = (int)((keep >> ii) & 1ull);
    }
    __syncthreads();

    // Inclusive prefix sum over keep flags (Hillis-Steele)
    scan[tid] = keepf[tid];
    __syncthreads();
    for (int off = 1; off < 1024; off <<= 1) {
        int add = (tid >= off) ? scan[tid - off] : 0;
        __syncthreads();
        scan[tid] += add;
        __syncthreads();
    }

    float* ob = out;                                  // [16][300][4]
    float* os = out + (size_t)BATCH * MAXDET * 4;     // [16][300]
    float* ol = out + (size_t)BATCH * MAXDET * 5;     // [16][300] labels as f32
    int total = scan[1023];

    if (tid < PRE && keepf[tid]) {
        int m = scan[tid] - 1;
        if (m < MAXDET) {
            float* p = ob + ((size_t)b * MAXDET + m) * 4;
            p[0] = rbx1[tid]; p[1] = rby1[tid]; p[2] = rbx2[tid]; p[3] = rby2[tid];
            os[b * MAXDET + m] = ssc[tid];
            ol[b * MAXDET + m] = (float)slb[tid];
        }
    }
    for (int m = tid; m < MAXDET; m += 1024) {
        if (m >= total) {
            float* p = ob + ((size_t)b * MAXDET + m) * 4;
            p[0] = 0.0f; p[1] = 0.0f; p[2] = 0.0f; p[3] = 0.0f;
            os[b * MAXDET + m] = 0.0f;
            ol[b * MAXDET + m] = -1.0f;
        }
    }
}

extern "C" void kernel_launch(void* const* d_in, const int* in_sizes, int n_in,
                              void* d_out, int out_size) {
    (void)in_sizes; (void)n_in; (void)out_size;
    const float* preds = (const float*)d_in[0];
    float* out = (float*)d_out;

    cudaFuncSetAttribute(final_kernel,
                         cudaFuncAttributeMaxDynamicSharedMemorySize, SMEM_FINAL);

    reset_kernel<<<1, 32>>>();
    dim3 gc((ANCH + 255) / 256, BATCH);
    conf_kernel<<<gc, 256>>>(preds);
    cand_kernel<<<dim3(30, BATCH), 256>>>(preds);
    need_kernel<<<1, 32>>>();
    fallback_kernel<<<dim3(256, BATCH), 256>>>(preds);
    final_kernel<<<BATCH, 1024, SMEM_FINAL>>>(preds, out);
}

// round 2
// speedup vs baseline: 1.9237x; 1.9237x over previous
#include <cuda_runtime.h>

#define BATCH 16
#define ANCH 22743
#define ROW 85
#define NCLS 80
#define NSC (ANCH * NCLS)
#define CAP 16384
#define PRE 1000
#define MAXDET 300
#define CONF_THRESH 0.2f
#define PRE_THRESH 0.9f
#define NMS_THRESH 0.45f
#define MAXK 64
#define NB 6144
#define BOFF 0x3E000000u
#define SORTN 2048

// ---------------- device scratch (no allocations allowed) ----------------
__device__ int g_cnt0[BATCH];
__device__ int g_cnt1[BATCH];
__device__ unsigned long long g_cand[BATCH][CAP];

struct SMFinal {
    unsigned long long keys[SORTN];
    int hist[NB];
    int rsum[1024];
    float rbx1[1024], rby1[1024], rbx2[1024], rby2[1024];
    float sx1[1024], sy1[1024], sx2[1024], sy2[1024], sar[1024];
    float ssc[1024];
    int slb[1024];
    int clist[NCLS * MAXK];
    int ccnt[NCLS];
    int keepf[1024];
    int scan[1024];
    int cstar, ccount2, smax;
};

__global__ void reset_kernel() {
    int t = threadIdx.x;
    if (t < BATCH) { g_cnt0[t] = 0; g_cnt1[t] = 0; }
}

// Fused: conf prefilter + cooperative class scoring + candidate emission (> 0.9)
__global__ void scan_kernel(const float* __restrict__ preds) {
    int b = blockIdx.y;
    int a0 = blockIdx.x * blockDim.x + threadIdx.x;
    int lane = threadIdx.x & 31;
    bool inb = a0 < ANCH;
    float conf0 = inb ? preds[((size_t)b * ANCH + a0) * ROW + 4] : 0.0f;
    unsigned m = __ballot_sync(0xffffffffu, inb && (conf0 > PRE_THRESH));
    while (m) {
        int src = __ffs(m) - 1;
        m &= m - 1;
        int a = __shfl_sync(0xffffffffu, a0, src);
        float conf = __shfl_sync(0xffffffffu, conf0, src);
        const float* row = preds + ((size_t)b * ANCH + a) * ROW;
#pragma unroll
        for (int part = 0; part < 3; part++) {
            int k = part * 32 + lane;
            float p = (k < NCLS) ? row[5 + k] : 0.0f;
            float s = __fmul_rn(p, conf);
            bool pr = (k < NCLS) && (s > PRE_THRESH);
            unsigned mm = __ballot_sync(0xffffffffu, pr);
            if (pr) {
                int leader = __ffs(mm) - 1;
                int rank = __popc(mm & ((1u << lane) - 1u));
                int basep;
                if (lane == leader) basep = atomicAdd(&g_cnt0[b], __popc(mm));
                basep = __shfl_sync(mm, basep, leader);
                int pos = basep + rank;
                if (pos < CAP) {
                    unsigned flat = (unsigned)a * 80u + (unsigned)k;
                    g_cand[b][pos] =
                        ((unsigned long long)__float_as_uint(s) << 32) |
                        (unsigned long long)(~flat);
                }
            }
        }
    }
}

// Safety net (normally exits immediately): append scores in (0.2, 0.9].
// Uses its own counter g_cnt1 so the trigger condition (g_cnt0) is race-free.
__global__ void fallback_kernel(const float* __restrict__ preds) {
    int b = blockIdx.y;
    int base = min(g_cnt0[b], CAP);
    if (base >= PRE) return;
    const float* bp = preds + (size_t)b * ANCH * ROW;
    int tid0 = blockIdx.x * blockDim.x + threadIdx.x;
    int stride = gridDim.x * blockDim.x;
    int lane = threadIdx.x & 31;
    const int NRUP = ((NSC + 31) & ~31);
    for (int i = tid0; i < NRUP; i += stride) {
        bool inb = i < NSC;
        float s = 0.0f;
        unsigned flat = (unsigned)i;
        if (inb) {
            unsigned a = flat / 80u;
            unsigned k = flat - a * 80u;
            float conf = bp[(size_t)a * ROW + 4];
            float p = bp[(size_t)a * ROW + 5 + k];
            s = __fmul_rn(p, conf);
        }
        bool pred = inb && (s > CONF_THRESH) && !(s > PRE_THRESH);
        unsigned m = __ballot_sync(0xffffffffu, pred);
        if (pred) {
            int leader = __ffs(m) - 1;
            int rank = __popc(m & ((1u << lane) - 1u));
            int basep;
            if (lane == leader) basep = atomicAdd(&g_cnt1[b], __popc(m));
            basep = __shfl_sync(m, basep, leader);
            int pos = base + basep + rank;
            if (pos < CAP)
                g_cand[b][pos] =
                    ((unsigned long long)__float_as_uint(s) << 32) |
                    (unsigned long long)(~flat);
        }
    }
}

// Per-image: histogram-select top~1000, sort 2048, per-class NMS, emit top-300
__global__ void __launch_bounds__(1024, 1)
final_kernel(const float* __restrict__ preds, float* __restrict__ out) {
    extern __shared__ char smc[];
    SMFinal& sm = *(SMFinal*)smc;
    int b = blockIdx.x;
    int tid = threadIdx.x;

    int n = min(min(g_cnt0[b], CAP) + g_cnt1[b], CAP);

    for (int i = tid; i < SORTN; i += 1024) sm.keys[i] = 0ull;
    for (int i = tid; i < NB; i += 1024) sm.hist[i] = 0;
    if (tid < NCLS) sm.ccnt[tid] = 0;
    sm.keepf[tid] = 0;
    if (tid == 0) { sm.smax = 0; sm.ccount2 = 0; sm.cstar = NB; }
    __syncthreads();

    // Histogram of score bits (monotone buckets for positive floats)
    for (int i = tid; i < n; i += 1024) {
        unsigned sb = (unsigned)(g_cand[b][i] >> 32);
        int bk = min((int)((sb - BOFF) >> 12), NB - 1);
        atomicAdd(&sm.hist[bk], 1);
    }
    __syncthreads();

    int t_target = min(PRE, n);

    // Per-thread group sums (6 buckets each), reverse inclusive scan
    {
        int s6 = 0;
#pragma unroll
        for (int q = 0; q < 6; q++) s6 += sm.hist[tid * 6 + q];
        sm.rsum[tid] = s6;
    }
    __syncthreads();
    for (int off = 1; off < 1024; off <<= 1) {
        int add = (tid + off < 1024) ? sm.rsum[tid + off] : 0;
        __syncthreads();
        sm.rsum[tid] += add;
        __syncthreads();
    }

    // Find cutoff bucket: smallest bucket index with suffix count >= t_target
    if (t_target > 0 && sm.rsum[tid] >= t_target &&
        (tid == 1023 || sm.rsum[tid + 1] < t_target)) {
        int acc = (tid < 1023) ? sm.rsum[tid + 1] : 0;
        for (int bk = tid * 6 + 5; bk >= tid * 6; bk--) {
            acc += sm.hist[bk];
            if (acc >= t_target) { sm.cstar = bk; break; }
        }
    }
    __syncthreads();
    int cstar = sm.cstar;

    // Compact candidates at/above cutoff into the sort array
    for (int i = tid; i < n; i += 1024) {
        unsigned long long key = g_cand[b][i];
        unsigned sb = (unsigned)(key >> 32);
        int bk = min((int)((sb - BOFF) >> 12), NB - 1);
        if (bk >= cstar) {
            int pos = atomicAdd(&sm.ccount2, 1);
            if (pos < SORTN) sm.keys[pos] = key;
        }
    }
    __syncthreads();

    // Bitonic sort ascending (zero padding sinks; warp-local stages for j<=16)
    for (int k = 2; k <= SORTN; k <<= 1) {
        for (int j = k >> 1; j > 0; j >>= 1) {
            if (j >= 32) __syncthreads(); else __syncwarp();
            int pos = ((tid & ~(j - 1)) << 1) | (tid & (j - 1));
            int par = pos | j;
            unsigned long long va = sm.keys[pos], vb = sm.keys[par];
            bool up = ((pos & k) == 0);
            if ((va > vb) == up) { sm.keys[pos] = vb; sm.keys[par] = va; }
        }
    }
    __syncthreads();

    // Decode top-1000 (descending)
    {
        int j = tid;
        unsigned long long key = (j < PRE) ? sm.keys[SORTN - 1 - j] : 0ull;
        float sc = -1.0f;
        unsigned flat = 0u;
        if (j < PRE && key != 0ull) {
            sc = __uint_as_float((unsigned)(key >> 32));
            flat = ~((unsigned)(key & 0xffffffffull));
        }
        unsigned a = flat / 80u;
        unsigned lbl = flat - a * 80u;
        if (a >= ANCH) { a = 0; lbl = 0; }
        const float* row = preds + ((size_t)b * ANCH + a) * ROW;
        float b0 = row[0], b1 = row[1], b2 = row[2], b3 = row[3];
        sm.rbx1[j] = b0; sm.rby1[j] = b1; sm.rbx2[j] = b2; sm.rby2[j] = b3;
        sm.ssc[j] = sc;
        sm.slb[j] = (int)lbl;
        if (j < PRE) {
            float mx = fmaxf(fmaxf(b0, b1), fmaxf(b2, b3));
            atomicMax(&sm.smax, __float_as_int(mx));  // coords >= 0
        }
    }
    __syncthreads();

    float M = __int_as_float(sm.smax);
    float shb = __fadd_rn(M, 1.0f);
    {
        int j = tid;
        float sh = __fmul_rn((float)sm.slb[j], shb);
        float x1 = __fadd_rn(sm.rbx1[j], sh);
        float y1 = __fadd_rn(sm.rby1[j], sh);
        float x2 = __fadd_rn(sm.rbx2[j], sh);
        float y2 = __fadd_rn(sm.rby2[j], sh);
        sm.sx1[j] = x1; sm.sy1[j] = y1; sm.sx2[j] = x2; sm.sy2[j] = y2;
        sm.sar[j] = __fmul_rn(fmaxf(__fsub_rn(x2, x1), 0.0f),
                              fmaxf(__fsub_rn(y2, y1), 0.0f));
    }
    __syncthreads();

    // Stable per-class grouping (warp 0, ascending j = descending score)
    if ((tid >> 5) == 0) {
        int lane = tid & 31;
        for (int jb = 0; jb < PRE; jb += 32) {
            int j = jb + lane;
            bool act = j < PRE;
            int lbl = act ? sm.slb[j] : -1;
            unsigned m = __match_any_sync(0xffffffffu, lbl);
            if (act) {
                int leader = __ffs(m) - 1;
                int rank = __popc(m & ((1u << lane) - 1u));
                int basep;
                if (lane == leader) basep = sm.ccnt[lbl];
                basep = __shfl_sync(m, basep, leader);
                int pos = basep + rank;
                if (pos < MAXK) sm.clist[lbl * MAXK + pos] = j;
                if (lane == leader) sm.ccnt[lbl] = basep + __popc(m);
            }
            __syncwarp();
        }
    }
    __syncthreads();

    // Per-class greedy NMS (cross-class shifted IoU is exactly 0)
    if (tid < NCLS) {
        int c = tid;
        int kc = min(sm.ccnt[c], MAXK);
        unsigned long long keep = 0ull;
        for (int ii = 0; ii < kc; ii++) {
            int j = sm.clist[c * MAXK + ii];
            if (sm.ssc[j] > CONF_THRESH) keep |= (1ull << ii);
        }
        for (int ii = 0; ii < kc; ii++) {
            if (!((keep >> ii) & 1ull)) continue;
            int ji = sm.clist[c * MAXK + ii];
            float ax1 = sm.sx1[ji], ay1 = sm.sy1[ji];
            float ax2 = sm.sx2[ji], ay2 = sm.sy2[ji];
            float aar = sm.sar[ji];
            for (int jj = ii + 1; jj < kc; jj++) {
                if (!((keep >> jj) & 1ull)) continue;
                int j2 = sm.clist[c * MAXK + jj];
                float ix1 = fmaxf(ax1, sm.sx1[j2]);
                float iy1 = fmaxf(ay1, sm.sy1[j2]);
                float ix2 = fminf(ax2, sm.sx2[j2]);
                float iy2 = fminf(ay2, sm.sy2[j2]);
                float iw = fmaxf(__fsub_rn(ix2, ix1), 0.0f);
                float ih = fmaxf(__fsub_rn(iy2, iy1), 0.0f);
                float inter = __fmul_rn(iw, ih);
                float den = __fadd_rn(
                    __fsub_rn(__fadd_rn(aar, sm.sar[j2]), inter), 1e-7f);
                float iou = __fdiv_rn(inter, den);
                if (iou > NMS_THRESH) keep &= ~(1ull << jj);
            }
        }
        for (int ii = 0; ii < kc; ii++)
            sm.keepf[sm.clist[c * MAXK + ii]] = (int)((keep >> ii) & 1ull);
    }
    __syncthreads();

    // Inclusive prefix sum over keep flags
    sm.scan[tid] = sm.keepf[tid];
    __syncthreads();
    for (int off = 1; off < 1024; off <<= 1) {
        int add = (tid >= off) ? sm.scan[tid - off] : 0;
        __syncthreads();
        sm.scan[tid] += add;
        __syncthreads();
    }

    float* ob = out;                               // [16][300][4]
    float* os = out + (size_t)BATCH * MAXDET * 4;  // [16][300]
    float* ol = out + (size_t)BATCH * MAXDET * 5;  // [16][300] labels as f32
    int total = sm.scan[1023];

    if (tid < PRE && sm.keepf[tid]) {
        int m = sm.scan[tid] - 1;
        if (m < MAXDET) {
            float* p = ob + ((size_t)b * MAXDET + m) * 4;
            p[0] = sm.rbx1[tid]; p[1] = sm.rby1[tid];
            p[2] = sm.rbx2[tid]; p[3] = sm.rby2[tid];
            os[b * MAXDET + m] = sm.ssc[tid];
            ol[b * MAXDET + m] = (float)sm.slb[tid];
        }
    }
    for (int m = tid; m < MAXDET; m += 1024) {
        if (m >= total) {
            float* p = ob + ((size_t)b * MAXDET + m) * 4;
            p[0] = 0.0f; p[1] = 0.0f; p[2] = 0.0f; p[3] = 0.0f;
            os[b * MAXDET + m] = 0.0f;
            ol[b * MAXDET + m] = -1.0f;
        }
    }
}

extern "C" void kernel_launch(void* const* d_in, const int* in_sizes, int n_in,
                              void* d_out, int out_size) {
    (void)in_sizes; (void)n_in; (void)out_size;
    const float* preds = (const float*)d_in[0];
    float* out = (float*)d_out;

    cudaFuncSetAttribute(final_kernel,
                         cudaFuncAttributeMaxDynamicSharedMemorySize,
                         (int)sizeof(SMFinal));

    reset_kernel<<<1, 32>>>();
    scan_kernel<<<dim3((ANCH + 255) / 256, BATCH), 256>>>(preds);
    fallback_kernel<<<dim3(64, BATCH), 256>>>(preds);
    final_kernel<<<BATCH, 1024, sizeof(SMFinal)>>>(preds, out);
}

// round 3
// speedup vs baseline: 2.0850x; 1.0839x over previous
#include <cuda_runtime.h>

#define BATCH 16
#define ANCH 22743
#define ROW 85
#define NCLS 80
#define NSC (ANCH * NCLS)
#define ABLK 89            // ceil(ANCH / 256)
#define SEGW 1024          // candidate slots per scan block
#define PRE 1000
#define MAXDET 300
#define CONF_THRESH 0.2f
#define PRE_THRESH 0.9f
#define NMS_THRESH 0.45f
#define MAXK 64
#define NB 6144
#define BOFF 0x3E000000u
#define SORTN 2048

// ---------------- device scratch (static; no allocations) ----------------
__device__ unsigned long long g_cand[BATCH][ABLK * SEGW];
__device__ int g_bcnt[BATCH][ABLK];

struct SMF {
    unsigned long long keys[SORTN];   // compacted candidates near/above cutoff
    unsigned long long skeys[1024];   // rank-ordered top-1000 keys
    int hist[NB];
    int rsum[1024];
    int wred[33];
    float rbx1[1024], rby1[1024], rbx2[1024], rby2[1024];
    float sx1[1024], sy1[1024], sx2[1024], sy2[1024], sar[1024];
    float ssc[1024];
    int slb[1024];
    int clist[NCLS * MAXK];
    int ccnt[NCLS];
    int keepf[1024];
    int wscan[33];
    int n_tot, over, cstar, mcnt, smax, total;
};

// Per-block-segment candidate scan: conf>0.9 prefilter, warp-cooperative
// class scoring, emission of s>0.9 candidates. Shared counter -> no reset.
__global__ void scan_kernel(const float* __restrict__ preds) {
    __shared__ int s_cnt;
    int b = blockIdx.y;
    int c = blockIdx.x;
    if (threadIdx.x == 0) s_cnt = 0;
    __syncthreads();
    int a0 = c * 256 + threadIdx.x;
    int lane = threadIdx.x & 31;
    bool inb = a0 < ANCH;
    float conf0 = inb ? preds[((size_t)b * ANCH + a0) * ROW + 4] : 0.0f;
    unsigned m = __ballot_sync(0xffffffffu, inb && (conf0 > PRE_THRESH));
    unsigned long long* seg = g_cand[b] + c * SEGW;
    while (m) {
        int src = __ffs(m) - 1;
        m &= m - 1;
        int a = __shfl_sync(0xffffffffu, a0, src);
        float conf = __shfl_sync(0xffffffffu, conf0, src);
        const float* row = preds + ((size_t)b * ANCH + a) * ROW;
#pragma unroll
        for (int part = 0; part < 3; part++) {
            int k = part * 32 + lane;
            float p = (k < NCLS) ? row[5 + k] : 0.0f;
            float s = __fmul_rn(p, conf);
            bool pr = (k < NCLS) && (s > PRE_THRESH);
            unsigned mm = __ballot_sync(0xffffffffu, pr);
            if (pr) {
                int leader = __ffs(mm) - 1;
                int rank = __popc(mm & ((1u << lane) - 1u));
                int basep;
                if (lane == leader) basep = atomicAdd(&s_cnt, __popc(mm));
                basep = __shfl_sync(mm, basep, leader);
                int pos = basep + rank;
                if (pos < SEGW) {
                    unsigned flat = (unsigned)a * 80u + (unsigned)k;
                    seg[pos] =
                        ((unsigned long long)__float_as_uint(s) << 32) |
                        (unsigned long long)(~flat);
                }
            }
        }
    }
    __syncthreads();
    if (threadIdx.x == 0) g_bcnt[b][c] = s_cnt;  // true (unsaturated) count
}

__device__ __forceinline__ int bucket_of(unsigned sb) {
    return min((int)((sb - BOFF) >> 12), NB - 1);
}

__global__ void __launch_bounds__(1024, 1)
final_kernel(const float* __restrict__ preds, float* __restrict__ out) {
    extern __shared__ char smc[];
    SMF& sm = *(SMF*)smc;
    int b = blockIdx.x;
    int tid = threadIdx.x;
    int lane = tid & 31;
    int wid = tid >> 5;

    // ---- init ----
    for (int i = tid; i < SORTN; i += 1024) sm.keys[i] = 0ull;
    sm.skeys[tid] = 0ull;
#pragma unroll
    for (int q = 0; q < NB / 1024; q++) sm.hist[tid + q * 1024] = 0;
    if (tid < NCLS) sm.ccnt[tid] = 0;
    sm.keepf[tid] = 0;
    if (tid == 0) {
        sm.n_tot = 0; sm.over = 0; sm.cstar = NB; sm.mcnt = 0; sm.smax = 0;
    }
    __syncthreads();

    // ---- totals / slow-path decision ----
    if (tid < ABLK) {
        int v = g_bcnt[b][tid];
        atomicAdd(&sm.n_tot, v);
        if (v > SEGW) atomicOr(&sm.over, 1);
    }
    __syncthreads();
    bool slow = (sm.n_tot < PRE) || sm.over;

    // ---- histogram of score bits (monotone for positive floats) ----
    if (!slow) {
        for (int c = wid; c < ABLK; c += 32) {
            int cnt = g_bcnt[b][c];
            const unsigned long long* seg = g_cand[b] + c * SEGW;
            for (int i = lane; i < cnt; i += 32)
                atomicAdd(&sm.hist[bucket_of((unsigned)(seg[i] >> 32))], 1);
        }
    } else {
        const float* bp = preds + (size_t)b * ANCH * ROW;
        for (int i = tid; i < NSC; i += 1024) {
            int a = i / 80, k = i - a * 80;
            float s = __fmul_rn(bp[(size_t)a * ROW + 5 + k], bp[(size_t)a * ROW + 4]);
            if (s > CONF_THRESH)
                atomicAdd(&sm.hist[bucket_of(__float_as_uint(s))], 1);
        }
    }
    __syncthreads();

    // ---- suffix sums over 6-bucket groups (warp shuffles) ----
    {
        int v = 0;
#pragma unroll
        for (int q = 0; q < 6; q++) v += sm.hist[tid * 6 + q];
#pragma unroll
        for (int off = 1; off < 32; off <<= 1) {
            int t = __shfl_down_sync(0xffffffffu, v, off);
            if (lane + off < 32) v += t;
        }
        if (lane == 0) sm.wred[wid] = v;  // warp totals... v at lane0 = warp sum
        __syncthreads();
        if (wid == 0) {
            int w = sm.wred[lane];
            __syncwarp();
#pragma unroll
            for (int off = 1; off < 32; off <<= 1) {
                int t = __shfl_down_sync(0xffffffffu, w, off);
                if (lane + off < 32) w += t;
            }
            sm.wred[lane] = w;  // inclusive suffix over warp totals
        }
        __syncthreads();
        int suffix = v + ((wid < 31) ? sm.wred[wid + 1] : 0);
        sm.rsum[tid] = suffix;
    }
    __syncthreads();

    int t_target = min(PRE, sm.rsum[0]);

    // ---- cutoff bucket: smallest bk with suffix count >= t_target ----
    if (t_target > 0 && sm.rsum[tid] >= t_target &&
        (tid == 1023 || sm.rsum[tid + 1] < t_target)) {
        int acc = (tid < 1023) ? sm.rsum[tid + 1] : 0;
        for (int bk = tid * 6 + 5; bk >= tid * 6; bk--) {
            acc += sm.hist[bk];
            if (acc >= t_target) { sm.cstar = bk; break; }
        }
    }
    __syncthreads();
    int cstar = sm.cstar;

    // ---- compact candidates at/above cutoff ----
    if (!slow) {
        for (int c = wid; c < ABLK; c += 32) {
            int cnt = g_bcnt[b][c];
            const unsigned long long* seg = g_cand[b] + c * SEGW;
            for (int i = lane; i < cnt; i += 32) {
                unsigned long long key = seg[i];
                if (bucket_of((unsigned)(key >> 32)) >= cstar) {
                    int pos = atomicAdd(&sm.mcnt, 1);
                    if (pos < SORTN) sm.keys[pos] = key;
                }
            }
        }
    } else {
        const float* bp = preds + (size_t)b * ANCH * ROW;
        for (int i = tid; i < NSC; i += 1024) {
            int a = i / 80, k = i - a * 80;
            float s = __fmul_rn(bp[(size_t)a * ROW + 5 + k], bp[(size_t)a * ROW + 4]);
            if (s > CONF_THRESH && bucket_of(__float_as_uint(s)) >= cstar) {
                int pos = atomicAdd(&sm.mcnt, 1);
                if (pos < SORTN)
                    sm.keys[pos] =
                        ((unsigned long long)__float_as_uint(s) << 32) |
                        (unsigned long long)(~(unsigned)i);
            }
        }
    }
    __syncthreads();

    // ---- exact rank by counting (keys unique); scatter top-1000 ----
    {
        int mC = min(sm.mcnt, SORTN);
        unsigned long long k1 = (tid < mC) ? sm.keys[tid] : 0ull;
        unsigned long long k2 = (tid + 1024 < mC) ? sm.keys[tid + 1024] : 0ull;
        int r1 = 0, r2 = 0;
        for (int j = 0; j < mC; j++) {
            unsigned long long kj = sm.keys[j];
            r1 += (kj > k1);
            r2 += (kj > k2);
        }
        if (tid < mC && r1 < PRE) sm.skeys[r1] = k1;
        if (tid + 1024 < mC && r2 < PRE) sm.skeys[r2] = k2;
    }
    __syncthreads();

    // ---- decode top-1000, gather boxes, block max ----
    {
        unsigned long long key = (tid < PRE) ? sm.skeys[tid] : 0ull;
        float sc = -1.0f;
        unsigned flat = 0u;
        if (tid < PRE && key != 0ull) {
            sc = __uint_as_float((unsigned)(key >> 32));
            flat = ~((unsigned)(key & 0xffffffffull));
        }
        unsigned a = flat / 80u;
        unsigned lbl = flat - a * 80u;
        if (a >= ANCH) { a = 0; lbl = 0; }
        const float* row = preds + ((size_t)b * ANCH + a) * ROW;
        float b0 = row[0], b1 = row[1], b2 = row[2], b3 = row[3];
        sm.rbx1[tid] = b0; sm.rby1[tid] = b1; sm.rbx2[tid] = b2; sm.rby2[tid] = b3;
        sm.ssc[tid] = sc;
        sm.slb[tid] = (int)lbl;
        if (tid < PRE) {
            float mx = fmaxf(fmaxf(b0, b1), fmaxf(b2, b3));
            atomicMax(&sm.smax, __float_as_int(mx));  // coords >= 0
        }
    }
    __syncthreads();

    // ---- class shift (bit-exact reference arithmetic) ----
    {
        float M = __int_as_float(sm.smax);
        float shb = __fadd_rn(M, 1.0f);
        float sh = __fmul_rn((float)sm.slb[tid], shb);
        float x1 = __fadd_rn(sm.rbx1[tid], sh);
        float y1 = __fadd_rn(sm.rby1[tid], sh);
        float x2 = __fadd_rn(sm.rbx2[tid], sh);
        float y2 = __fadd_rn(sm.rby2[tid], sh);
        sm.sx1[tid] = x1; sm.sy1[tid] = y1; sm.sx2[tid] = x2; sm.sy2[tid] = y2;
        sm.sar[tid] = __fmul_rn(fmaxf(__fsub_rn(x2, x1), 0.0f),
                                fmaxf(__fsub_rn(y2, y1), 0.0f));
    }
    __syncthreads();

    // ---- stable per-class grouping via counting (barrier-free) ----
    {
        int mylbl = sm.slb[tid];
        int lim = min(tid, PRE);
        int pos = 0;
        for (int t = 0; t < lim; t++) pos += (sm.slb[t] == mylbl);
        if (tid < PRE) {
            atomicAdd(&sm.ccnt[mylbl], 1);
            if (pos < MAXK) sm.clist[mylbl * MAXK + pos] = tid;
        }
    }
    __syncthreads();

    // ---- per-class greedy NMS (cross-class shifted IoU exactly 0) ----
    if (tid < NCLS) {
        int c = tid;
        int kc = min(sm.ccnt[c], MAXK);
        unsigned long long keep = 0ull;
        for (int ii = 0; ii < kc; ii++) {
            int j = sm.clist[c * MAXK + ii];
            if (sm.ssc[j] > CONF_THRESH) keep |= (1ull << ii);
        }
        for (int ii = 0; ii < kc; ii++) {
            if (!((keep >> ii) & 1ull)) continue;
            int ji = sm.clist[c * MAXK + ii];
            float ax1 = sm.sx1[ji], ay1 = sm.sy1[ji];
            float ax2 = sm.sx2[ji], ay2 = sm.sy2[ji];
            float aar = sm.sar[ji];
            for (int jj = ii + 1; jj < kc; jj++) {
                if (!((keep >> jj) & 1ull)) continue;
                int j2 = sm.clist[c * MAXK + jj];
                float ix1 = fmaxf(ax1, sm.sx1[j2]);
                float iy1 = fmaxf(ay1, sm.sy1[j2]);
                float ix2 = fminf(ax2, sm.sx2[j2]);
                float iy2 = fminf(ay2, sm.sy2[j2]);
                float iw = fmaxf(__fsub_rn(ix2, ix1), 0.0f);
                float ih = fmaxf(__fsub_rn(iy2, iy1), 0.0f);
                float inter = __fmul_rn(iw, ih);
                float den = __fadd_rn(
                    __fsub_rn(__fadd_rn(aar, sm.sar[j2]), inter), 1e-7f);
                float iou = __fdiv_rn(inter, den);
                if (iou > NMS_THRESH) keep &= ~(1ull << jj);
            }
        }
        for (int ii = 0; ii < kc; ii++)
            sm.keepf[sm.clist[c * MAXK + ii]] = (int)((keep >> ii) & 1ull);
    }
    __syncthreads();

    // ---- keep-flag prefix sum (warp shuffles) ----
    int myscan, total;
    {
        int p = sm.keepf[tid];
#pragma unroll
        for (int off = 1; off < 32; off <<= 1) {
            int t = __shfl_up_sync(0xffffffffu, p, off);
            if (lane >= off) p += t;
        }
        if (lane == 31) sm.wscan[wid] = p;
        __syncthreads();
        if (wid == 0) {
            int w = sm.wscan[lane];
            __syncwarp();
#pragma unroll
            for (int off = 1; off < 32; off <<= 1) {
                int t = __shfl_up_sync(0xffffffffu, w, off);
                if (lane >= off) w += t;
            }
            sm.wscan[lane] = w;  // inclusive over warp totals
        }
        __syncthreads();
        int base = (wid > 0) ? sm.wscan[wid - 1] : 0;
        myscan = base + p;  // inclusive over block
        total = sm.wscan[31];
    }

    // ---- emit top-300 ----
    float* ob = out;                               // [16][300][4]
    float* os = out + (size_t)BATCH * MAXDET * 4;  // [16][300]
    float* ol = out + (size_t)BATCH * MAXDET * 5;  // [16][300] labels as f32

    if (tid < PRE && sm.keepf[tid]) {
        int m = myscan - 1;
        if (m < MAXDET) {
            float* p = ob + ((size_t)b * MAXDET + m) * 4;
            p[0] = sm.rbx1[tid]; p[1] = sm.rby1[tid];
            p[2] = sm.rbx2[tid]; p[3] = sm.rby2[tid];
            os[b * MAXDET + m] = sm.ssc[tid];
            ol[b * MAXDET + m] = (float)sm.slb[tid];
        }
    }
    for (int m = tid; m < MAXDET; m += 1024) {
        if (m >= total) {
            float* p = ob + ((size_t)b * MAXDET + m) * 4;
            p[0] = 0.0f; p[1] = 0.0f; p[2] = 0.0f; p[3] = 0.0f;
            os[b * MAXDET + m] = 0.0f;
            ol[b * MAXDET + m] = -1.0f;
        }
    }
}

extern "C" void kernel_launch(void* const* d_in, const int* in_sizes, int n_in,
                              void* d_out, int out_size) {
    (void)in_sizes; (void)n_in; (void)out_size;
    const float* preds = (const float*)d_in[0];
    float* out = (float*)d_out;

    cudaFuncSetAttribute(final_kernel,
                         cudaFuncAttributeMaxDynamicSharedMemorySize,
                         (int)sizeof(SMF));

    scan_kernel<<<dim3(ABLK, BATCH), 256>>>(preds);
    final_kernel<<<BATCH, 1024, sizeof(SMF)>>>(preds, out);
}

// round 4
// speedup vs baseline: 2.8200x; 1.3525x over previous
#include <cuda_runtime.h>

#define BATCH 16
#define ANCH 22743
#define ROW 85
#define NCLS 80
#define NSC (ANCH * NCLS)
#define ABLK 89            // ceil(ANCH / 256)
#define SEGW 1024          // candidate slots per scan block
#define PRE 1000
#define MAXDET 300
#define CONF_THRESH 0.2f
#define PRE_THRESH 0.9f
#define NMS_THRESH 0.45f
#define MAXK 64
#define NB 6144
#define BOFF 0x3E000000u
#define SORTN 2048

// ---------------- device scratch (static; no allocations) ----------------
__device__ unsigned long long g_cand[BATCH][ABLK * SEGW];
__device__ int g_bcnt[BATCH][ABLK];

struct SMF {
    unsigned long long keys[SORTN];   // bucket-grouped candidates >= cutoff
    unsigned long long skeys[1024];   // rank-ordered top-1000 keys
    int hist[NB];
    int bpos[NB];                     // per-bucket scatter counters
    int rsum[1024];                   // per-6-bucket-group inclusive suffix
    int wred[33];
    int wcnt[32 * NCLS];              // per-warp per-class counts
    float rbx1[1024], rby1[1024], rbx2[1024], rby2[1024];
    float sx1[1024], sy1[1024], sx2[1024], sy2[1024], sar[1024];
    float ssc[1024];
    int slb[1024];
    int clist[NCLS * MAXK];
    int keepf[1024];
    int wscan[33];
    int n_tot, over, cstar, mcnt, smax;
};

// Per-block-segment candidate scan: conf>0.9 prefilter, warp-cooperative
// class scoring, emission of s>0.9 candidates. Shared counter -> no reset.
__global__ void scan_kernel(const float* __restrict__ preds) {
    __shared__ int s_cnt;
    int b = blockIdx.y;
    int c = blockIdx.x;
    if (threadIdx.x == 0) s_cnt = 0;
    __syncthreads();
    int a0 = c * 256 + threadIdx.x;
    int lane = threadIdx.x & 31;
    bool inb = a0 < ANCH;
    float conf0 = inb ? preds[((size_t)b * ANCH + a0) * ROW + 4] : 0.0f;
    unsigned m = __ballot_sync(0xffffffffu, inb && (conf0 > PRE_THRESH));
    unsigned long long* seg = g_cand[b] + c * SEGW;
    while (m) {
        int src = __ffs(m) - 1;
        m &= m - 1;
        int a = __shfl_sync(0xffffffffu, a0, src);
        float conf = __shfl_sync(0xffffffffu, conf0, src);
        const float* row = preds + ((size_t)b * ANCH + a) * ROW;
#pragma unroll
        for (int part = 0; part < 3; part++) {
            int k = part * 32 + lane;
            float p = (k < NCLS) ? row[5 + k] : 0.0f;
            float s = __fmul_rn(p, conf);
            bool pr = (k < NCLS) && (s > PRE_THRESH);
            unsigned mm = __ballot_sync(0xffffffffu, pr);
            if (pr) {
                int leader = __ffs(mm) - 1;
                int rank = __popc(mm & ((1u << lane) - 1u));
                int basep;
                if (lane == leader) basep = atomicAdd(&s_cnt, __popc(mm));
                basep = __shfl_sync(mm, basep, leader);
                int pos = basep + rank;
                if (pos < SEGW) {
                    unsigned flat = (unsigned)a * 80u + (unsigned)k;
                    seg[pos] =
                        ((unsigned long long)__float_as_uint(s) << 32) |
                        (unsigned long long)(~flat);
                }
            }
        }
    }
    __syncthreads();
    if (threadIdx.x == 0) g_bcnt[b][c] = s_cnt;  // true (unsaturated) count
}

__device__ __forceinline__ int bucket_of(unsigned sb) {
    return min((int)((sb - BOFF) >> 12), NB - 1);
}

// Count of histogram items in buckets >= bk (bk in [0, NB])
__device__ __forceinline__ int suffix_from(const SMF& sm, int bk) {
    if (bk >= NB) return 0;
    int g = bk / 6;
    int s = (g + 1 < 1024) ? sm.rsum[g + 1] : 0;
    int e = g * 6 + 6;
    for (int q = bk; q < e; q++) s += sm.hist[q];
    return s;
}

__global__ void __launch_bounds__(1024, 1)
final_kernel(const float* __restrict__ preds, float* __restrict__ out) {
    extern __shared__ char smc[];
    SMF& sm = *(SMF*)smc;
    int b = blockIdx.x;
    int tid = threadIdx.x;
    int lane = tid & 31;
    int wid = tid >> 5;

    // ---- init ----
    for (int i = tid; i < SORTN; i += 1024) sm.keys[i] = 0ull;
    sm.skeys[tid] = 0ull;
#pragma unroll
    for (int q = 0; q < NB / 1024; q++) {
        sm.hist[tid + q * 1024] = 0;
        sm.bpos[tid + q * 1024] = 0;
    }
    for (int i = tid; i < 32 * NCLS; i += 1024) sm.wcnt[i] = 0;
    sm.keepf[tid] = 0;
    if (tid == 0) { sm.n_tot = 0; sm.over = 0; sm.cstar = NB; sm.smax = 0; }
    __syncthreads();

    // ---- totals / slow-path decision ----
    if (tid < ABLK) {
        int v = g_bcnt[b][tid];
        atomicAdd(&sm.n_tot, v);
        if (v > SEGW) atomicOr(&sm.over, 1);
    }
    __syncthreads();
    bool slow = (sm.n_tot < PRE) || sm.over;

    // ---- histogram of score bits (monotone for positive floats) ----
    if (!slow) {
        for (int c = wid; c < ABLK; c += 32) {
            int cnt = g_bcnt[b][c];
            const unsigned long long* seg = g_cand[b] + c * SEGW;
            for (int i = lane; i < cnt; i += 32)
                atomicAdd(&sm.hist[bucket_of((unsigned)(seg[i] >> 32))], 1);
        }
    } else {
        const float* bp = preds + (size_t)b * ANCH * ROW;
        for (int i = tid; i < NSC; i += 1024) {
            int a = i / 80, k = i - a * 80;
            float s = __fmul_rn(bp[(size_t)a * ROW + 5 + k], bp[(size_t)a * ROW + 4]);
            if (s > CONF_THRESH)
                atomicAdd(&sm.hist[bucket_of(__float_as_uint(s))], 1);
        }
    }
    __syncthreads();

    // ---- suffix sums over 6-bucket groups (warp shuffles) ----
    {
        int v = 0;
#pragma unroll
        for (int q = 0; q < 6; q++) v += sm.hist[tid * 6 + q];
#pragma unroll
        for (int off = 1; off < 32; off <<= 1) {
            int t = __shfl_down_sync(0xffffffffu, v, off);
            if (lane + off < 32) v += t;
        }
        if (lane == 0) sm.wred[wid] = v;
        __syncthreads();
        if (wid == 0) {
            int w = sm.wred[lane];
            __syncwarp();
#pragma unroll
            for (int off = 1; off < 32; off <<= 1) {
                int t = __shfl_down_sync(0xffffffffu, w, off);
                if (lane + off < 32) w += t;
            }
            sm.wred[lane] = w;  // inclusive suffix over warp totals
        }
        __syncthreads();
        int suffix = v + ((wid < 31) ? sm.wred[wid + 1] : 0);
        sm.rsum[tid] = suffix;
    }
    __syncthreads();

    int t_target = min(PRE, sm.rsum[0]);

    // ---- cutoff bucket: smallest bk with suffix count >= t_target ----
    if (t_target > 0 && sm.rsum[tid] >= t_target &&
        (tid == 1023 || sm.rsum[tid + 1] < t_target)) {
        int acc = (tid < 1023) ? sm.rsum[tid + 1] : 0;
        for (int bk = tid * 6 + 5; bk >= tid * 6; bk--) {
            acc += sm.hist[bk];
            if (acc >= t_target) { sm.cstar = bk; break; }
        }
    }
    __syncthreads();
    int cstar = sm.cstar;
    if (tid == 0) sm.mcnt = suffix_from(sm, cstar);

    // ---- compact: scatter each passing key into its bucket's region ----
    // Region base of bucket bk = suffix(bk+1); regions partition [0, mcnt).
    if (!slow) {
        for (int c = wid; c < ABLK; c += 32) {
            int cnt = g_bcnt[b][c];
            const unsigned long long* seg = g_cand[b] + c * SEGW;
            for (int i = lane; i < cnt; i += 32) {
                unsigned long long key = seg[i];
                int bk = bucket_of((unsigned)(key >> 32));
                if (bk >= cstar) {
                    int slot = atomicAdd(&sm.bpos[bk], 1);
                    int pos = suffix_from(sm, bk + 1) + slot;
                    if (pos < SORTN) sm.keys[pos] = key;
                }
            }
        }
    } else {
        const float* bp = preds + (size_t)b * ANCH * ROW;
        for (int i = tid; i < NSC; i += 1024) {
            int a = i / 80, k = i - a * 80;
            float s = __fmul_rn(bp[(size_t)a * ROW + 5 + k], bp[(size_t)a * ROW + 4]);
            if (s > CONF_THRESH) {
                int bk = bucket_of(__float_as_uint(s));
                if (bk >= cstar) {
                    int slot = atomicAdd(&sm.bpos[bk], 1);
                    int pos = suffix_from(sm, bk + 1) + slot;
                    if (pos < SORTN)
                        sm.keys[pos] =
                            ((unsigned long long)__float_as_uint(s) << 32) |
                            (unsigned long long)(~(unsigned)i);
                }
            }
        }
    }
    __syncthreads();

    // ---- exact rank: bucket base + within-bucket count (keys unique) ----
    {
        int mC = min(sm.mcnt, SORTN);
#pragma unroll
        for (int it = 0; it < 2; it++) {
            int idx = tid + it * 1024;
            if (idx < mC) {
                unsigned long long key = sm.keys[idx];
                int bk = bucket_of((unsigned)(key >> 32));
                int base = suffix_from(sm, bk + 1);
                int end = min(base + sm.hist[bk], SORTN);
                int rank = base;
                for (int j = base; j < end; j++) rank += (sm.keys[j] > key);
                if (rank < PRE) sm.skeys[rank] = key;
            }
        }
    }
    __syncthreads();

    // ---- decode top-1000, gather boxes, block max ----
    {
        unsigned long long key = (tid < PRE) ? sm.skeys[tid] : 0ull;
        float sc = -1.0f;
        unsigned flat = 0u;
        if (tid < PRE && key != 0ull) {
            sc = __uint_as_float((unsigned)(key >> 32));
            flat = ~((unsigned)(key & 0xffffffffull));
        }
        unsigned a = flat / 80u;
        unsigned lbl = flat - a * 80u;
        if (a >= ANCH) { a = 0; lbl = 0; }
        const float* row = preds + ((size_t)b * ANCH + a) * ROW;
        float b0 = row[0], b1 = row[1], b2 = row[2], b3 = row[3];
        sm.rbx1[tid] = b0; sm.rby1[tid] = b1; sm.rbx2[tid] = b2; sm.rby2[tid] = b3;
        sm.ssc[tid] = sc;
        sm.slb[tid] = (int)lbl;
        if (tid < PRE) {
            float mx = fmaxf(fmaxf(b0, b1), fmaxf(b2, b3));
            atomicMax(&sm.smax, __float_as_int(mx));  // coords >= 0
        }
    }
    __syncthreads();

    // ---- class shift (bit-exact reference arithmetic) ----
    {
        float M = __int_as_float(sm.smax);
        float shb = __fadd_rn(M, 1.0f);
        float sh = __fmul_rn((float)sm.slb[tid], shb);
        float x1 = __fadd_rn(sm.rbx1[tid], sh);
        float y1 = __fadd_rn(sm.rby1[tid], sh);
        float x2 = __fadd_rn(sm.rbx2[tid], sh);
        float y2 = __fadd_rn(sm.rby2[tid], sh);
        sm.sx1[tid] = x1; sm.sy1[tid] = y1; sm.sx2[tid] = x2; sm.sy2[tid] = y2;
        sm.sar[tid] = __fmul_rn(fmaxf(__fsub_rn(x2, x1), 0.0f),
                                fmaxf(__fsub_rn(y2, y1), 0.0f));
    }

    // ---- stable per-class grouping: match_any + per-warp class counts ----
    int mylbl = (tid < PRE) ? sm.slb[tid] : -1;
    unsigned grpm = __match_any_sync(0xffffffffu, mylbl);
    int wrank = __popc(grpm & ((1u << lane) - 1u));
    if (tid < PRE && wrank == 0)
        sm.wcnt[wid * NCLS + mylbl] = __popc(grpm);
    __syncthreads();
    if (tid < PRE) {
        int base = 0;
        for (int w = 0; w < wid; w++) base += sm.wcnt[w * NCLS + mylbl];
        int pos = base + wrank;
        if (pos < MAXK) sm.clist[mylbl * MAXK + pos] = tid;
    }
    __syncthreads();

    // ---- per-class greedy NMS (cross-class shifted IoU exactly 0) ----
    if (tid < NCLS) {
        int c = tid;
        int kc = 0;
#pragma unroll 8
        for (int w = 0; w < 32; w++) kc += sm.wcnt[w * NCLS + c];
        kc = min(kc, MAXK);
        unsigned long long keep = 0ull;
        for (int ii = 0; ii < kc; ii++) {
            int j = sm.clist[c * MAXK + ii];
            if (sm.ssc[j] > CONF_THRESH) keep |= (1ull << ii);
        }
        for (int ii = 0; ii < kc; ii++) {
            if (!((keep >> ii) & 1ull)) continue;
            int ji = sm.clist[c * MAXK + ii];
            float ax1 = sm.sx1[ji], ay1 = sm.sy1[ji];
            float ax2 = sm.sx2[ji], ay2 = sm.sy2[ji];
            float aar = sm.sar[ji];
            for (int jj = ii + 1; jj < kc; jj++) {
                if (!((keep >> jj) & 1ull)) continue;
                int j2 = sm.clist[c * MAXK + jj];
                float ix1 = fmaxf(ax1, sm.sx1[j2]);
                float iy1 = fmaxf(ay1, sm.sy1[j2]);
                float ix2 = fminf(ax2, sm.sx2[j2]);
                float iy2 = fminf(ay2, sm.sy2[j2]);
                float iw = fmaxf(__fsub_rn(ix2, ix1), 0.0f);
                float ih = fmaxf(__fsub_rn(iy2, iy1), 0.0f);
                float inter = __fmul_rn(iw, ih);
                float den = __fadd_rn(
                    __fsub_rn(__fadd_rn(aar, sm.sar[j2]), inter), 1e-7f);
                float iou = __fdiv_rn(inter, den);
                if (iou > NMS_THRESH) keep &= ~(1ull << jj);
            }
        }
        for (int ii = 0; ii < kc; ii++)
            sm.keepf[sm.clist[c * MAXK + ii]] = (int)((keep >> ii) & 1ull);
    }
    __syncthreads();

    // ---- keep-flag prefix sum (warp shuffles) ----
    int myscan, total;
    {
        int p = sm.keepf[tid];
#pragma unroll
        for (int off = 1; off < 32; off <<= 1) {
            int t = __shfl_up_sync(0xffffffffu, p, off);
            if (lane >= off) p += t;
        }
        if (lane == 31) sm.wscan[wid] = p;
        __syncthreads();
        if (wid == 0) {
            int w = sm.wscan[lane];
            __syncwarp();
#pragma unroll
            for (int off = 1; off < 32; off <<= 1) {
                int t = __shfl_up_sync(0xffffffffu, w, off);
                if (lane >= off) w += t;
            }
            sm.wscan[lane] = w;
        }
        __syncthreads();
        int base = (wid > 0) ? sm.wscan[wid - 1] : 0;
        myscan = base + p;
        total = sm.wscan[31];
    }

    // ---- emit top-300 ----
    float* ob = out;                               // [16][300][4]
    float* os = out + (size_t)BATCH * MAXDET * 4;  // [16][300]
    float* ol = out + (size_t)BATCH * MAXDET * 5;  // [16][300] labels as f32

    if (tid < PRE && sm.keepf[tid]) {
        int m = myscan - 1;
        if (m < MAXDET) {
            float* p = ob + ((size_t)b * MAXDET + m) * 4;
            p[0] = sm.rbx1[tid]; p[1] = sm.rby1[tid];
            p[2] = sm.rbx2[tid]; p[3] = sm.rby2[tid];
            os[b * MAXDET + m] = sm.ssc[tid];
            ol[b * MAXDET + m] = (float)sm.slb[tid];
        }
    }
    for (int m = tid; m < MAXDET; m += 1024) {
        if (m >= total) {
            float* p = ob + ((size_t)b * MAXDET + m) * 4;
            p[0] = 0.0f; p[1] = 0.0f; p[2] = 0.0f; p[3] = 0.0f;
            os[b * MAXDET + m] = 0.0f;
            ol[b * MAXDET + m] = -1.0f;
        }
    }
}

extern "C" void kernel_launch(void* const* d_in, const int* in_sizes, int n_in,
                              void* d_out, int out_size) {
    (void)in_sizes; (void)n_in; (void)out_size;
    const float* preds = (const float*)d_in[0];
    float* out = (float*)d_out;

    cudaFuncSetAttribute(final_kernel,
                         cudaFuncAttributeMaxDynamicSharedMemorySize,
                         (int)sizeof(SMF));

    scan_kernel<<<dim3(ABLK, BATCH), 256>>>(preds);
    final_kernel<<<BATCH, 1024, sizeof(SMF)>>>(preds, out);
}

// round 5
// speedup vs baseline: 6.2156x; 2.2041x over previous
#include <cuda_runtime.h>

#define BATCH 16
#define ANCH 22743
#define ROW 85
#define NCLS 80
#define NSC (ANCH * NCLS)
#define ABLK 89            // ceil(ANCH / 256)
#define SEGW 1024          // candidate slots per scan block
#define PRE 1000
#define MAXDET 300
#define CONF_THRESH 0.2f
#define PRE_THRESH 0.9f
#define NMS_THRESH 0.45f
#define MAXK 64
#define NB 6144
#define BOFF 0x3E000000u
#define SORTN 2048
#define FULLM 0xffffffffu

// ---------------- device scratch (static; no allocations) ----------------
__device__ unsigned long long g_cand[BATCH][ABLK * SEGW];
__device__ int g_bcnt[BATCH][ABLK];

struct SMF {
    unsigned long long keys[SORTN];   // bucket-grouped candidates >= cutoff
    unsigned long long skeys[1024];   // rank-ordered top-1000 keys
    int hist[NB];
    int bpos[NB];                     // per-bucket scatter counters
    int rsum[1024];                   // per-6-bucket-group inclusive suffix
    int wred[33];
    int wcnt[32 * NCLS];              // per-warp per-class counts
    float rbx1[1024], rby1[1024], rbx2[1024], rby2[1024];
    float sx1[1024], sy1[1024], sx2[1024], sy2[1024], sar[1024];
    float ssc[1024];
    int slb[1024];
    int clist[NCLS * MAXK];
    int keepf[1024];
    int wscan[33];
    int n_tot, over, cstar, mcnt, smax;
};

// Per-block-segment candidate scan: conf>0.9 prefilter, warp-cooperative
// class scoring, emission of s>0.9 candidates. Shared counter -> no reset.
__global__ void scan_kernel(const float* __restrict__ preds) {
    __shared__ int s_cnt;
    int b = blockIdx.y;
    int c = blockIdx.x;
    if (threadIdx.x == 0) s_cnt = 0;
    __syncthreads();
    int a0 = c * 256 + threadIdx.x;
    int lane = threadIdx.x & 31;
    bool inb = a0 < ANCH;
    float conf0 = inb ? preds[((size_t)b * ANCH + a0) * ROW + 4] : 0.0f;
    unsigned m = __ballot_sync(FULLM, inb && (conf0 > PRE_THRESH));
    unsigned long long* seg = g_cand[b] + c * SEGW;
    while (m) {
        int src = __ffs(m) - 1;
        m &= m - 1;
        int a = __shfl_sync(FULLM, a0, src);
        float conf = __shfl_sync(FULLM, conf0, src);
        const float* row = preds + ((size_t)b * ANCH + a) * ROW;
#pragma unroll
        for (int part = 0; part < 3; part++) {
            int k = part * 32 + lane;
            float p = (k < NCLS) ? row[5 + k] : 0.0f;
            float s = __fmul_rn(p, conf);
            bool pr = (k < NCLS) && (s > PRE_THRESH);
            unsigned mm = __ballot_sync(FULLM, pr);
            if (pr) {
                int leader = __ffs(mm) - 1;
                int rank = __popc(mm & ((1u << lane) - 1u));
                int basep;
                if (lane == leader) basep = atomicAdd(&s_cnt, __popc(mm));
                basep = __shfl_sync(mm, basep, leader);
                int pos = basep + rank;
                if (pos < SEGW) {
                    unsigned flat = (unsigned)a * 80u + (unsigned)k;
                    seg[pos] =
                        ((unsigned long long)__float_as_uint(s) << 32) |
                        (unsigned long long)(~flat);
                }
            }
        }
    }
    __syncthreads();
    if (threadIdx.x == 0) g_bcnt[b][c] = s_cnt;  // true (unsaturated) count
}

__device__ __forceinline__ int bucket_of(unsigned sb) {
    return min((int)((sb - BOFF) >> 12), NB - 1);
}

// Count of histogram items in buckets >= bk (bk in [0, NB])
__device__ __forceinline__ int suffix_from(const SMF& sm, int bk) {
    if (bk >= NB) return 0;
    int g = bk / 6;
    int s = (g + 1 < 1024) ? sm.rsum[g + 1] : 0;
    int e = g * 6 + 6;
    for (int q = bk; q < e; q++) s += sm.hist[q];
    return s;
}

__global__ void __launch_bounds__(1024, 1)
final_kernel(const float* __restrict__ preds, float* __restrict__ out) {
    extern __shared__ char smc[];
    SMF& sm = *(SMF*)smc;
    int b = blockIdx.x;
    int tid = threadIdx.x;
    int lane = tid & 31;
    int wid = tid >> 5;

    // ---- init ----
    for (int i = tid; i < SORTN; i += 1024) sm.keys[i] = 0ull;
    sm.skeys[tid] = 0ull;
#pragma unroll
    for (int q = 0; q < NB / 1024; q++) {
        sm.hist[tid + q * 1024] = 0;
        sm.bpos[tid + q * 1024] = 0;
    }
    for (int i = tid; i < 32 * NCLS; i += 1024) sm.wcnt[i] = 0;
    sm.keepf[tid] = 0;
    if (tid == 0) { sm.n_tot = 0; sm.over = 0; sm.cstar = NB; sm.smax = 0; }
    __syncthreads();

    // ---- totals / slow-path decision ----
    if (tid < ABLK) {
        int v = g_bcnt[b][tid];
        atomicAdd(&sm.n_tot, v);
        if (v > SEGW) atomicOr(&sm.over, 1);
    }
    __syncthreads();
    bool slow = (sm.n_tot < PRE) || sm.over;

    // ---- histogram of score bits (monotone for positive floats) ----
    if (!slow) {
        for (int c = wid; c < ABLK; c += 32) {
            int cnt = g_bcnt[b][c];
            const unsigned long long* seg = g_cand[b] + c * SEGW;
            for (int i = lane; i < cnt; i += 32)
                atomicAdd(&sm.hist[bucket_of((unsigned)(seg[i] >> 32))], 1);
        }
    } else {
        const float* bp = preds + (size_t)b * ANCH * ROW;
        for (int i = tid; i < NSC; i += 1024) {
            int a = i / 80, k = i - a * 80;
            float s = __fmul_rn(bp[(size_t)a * ROW + 5 + k], bp[(size_t)a * ROW + 4]);
            if (s > CONF_THRESH)
                atomicAdd(&sm.hist[bucket_of(__float_as_uint(s))], 1);
        }
    }
    __syncthreads();

    // ---- suffix sums over 6-bucket groups (warp shuffles) ----
    {
        int v = 0;
#pragma unroll
        for (int q = 0; q < 6; q++) v += sm.hist[tid * 6 + q];
#pragma unroll
        for (int off = 1; off < 32; off <<= 1) {
            int t = __shfl_down_sync(FULLM, v, off);
            if (lane + off < 32) v += t;
        }
        if (lane == 0) sm.wred[wid] = v;
        __syncthreads();
        if (wid == 0) {
            int w = sm.wred[lane];
            __syncwarp();
#pragma unroll
            for (int off = 1; off < 32; off <<= 1) {
                int t = __shfl_down_sync(FULLM, w, off);
                if (lane + off < 32) w += t;
            }
            sm.wred[lane] = w;  // inclusive suffix over warp totals
        }
        __syncthreads();
        int suffix = v + ((wid < 31) ? sm.wred[wid + 1] : 0);
        sm.rsum[tid] = suffix;
    }
    __syncthreads();

    int t_target = min(PRE, sm.rsum[0]);

    // ---- cutoff bucket: smallest bk with suffix count >= t_target ----
    if (t_target > 0 && sm.rsum[tid] >= t_target &&
        (tid == 1023 || sm.rsum[tid + 1] < t_target)) {
        int acc = (tid < 1023) ? sm.rsum[tid + 1] : 0;
        for (int bk = tid * 6 + 5; bk >= tid * 6; bk--) {
            acc += sm.hist[bk];
            if (acc >= t_target) { sm.cstar = bk; break; }
        }
    }
    __syncthreads();
    int cstar = sm.cstar;
    if (tid == 0) sm.mcnt = suffix_from(sm, cstar);

    // ---- compact: scatter each passing key into its bucket's region ----
    if (!slow) {
        for (int c = wid; c < ABLK; c += 32) {
            int cnt = g_bcnt[b][c];
            const unsigned long long* seg = g_cand[b] + c * SEGW;
            for (int i = lane; i < cnt; i += 32) {
                unsigned long long key = seg[i];
                int bk = bucket_of((unsigned)(key >> 32));
                if (bk >= cstar) {
                    int slot = atomicAdd(&sm.bpos[bk], 1);
                    int pos = suffix_from(sm, bk + 1) + slot;
                    if (pos < SORTN) sm.keys[pos] = key;
                }
            }
        }
    } else {
        const float* bp = preds + (size_t)b * ANCH * ROW;
        for (int i = tid; i < NSC; i += 1024) {
            int a = i / 80, k = i - a * 80;
            float s = __fmul_rn(bp[(size_t)a * ROW + 5 + k], bp[(size_t)a * ROW + 4]);
            if (s > CONF_THRESH) {
                int bk = bucket_of(__float_as_uint(s));
                if (bk >= cstar) {
                    int slot = atomicAdd(&sm.bpos[bk], 1);
                    int pos = suffix_from(sm, bk + 1) + slot;
                    if (pos < SORTN)
                        sm.keys[pos] =
                            ((unsigned long long)__float_as_uint(s) << 32) |
                            (unsigned long long)(~(unsigned)i);
                }
            }
        }
    }
    __syncthreads();

    // ---- exact rank: bucket base + within-bucket count (keys unique) ----
    {
        int mC = min(sm.mcnt, SORTN);
#pragma unroll
        for (int it = 0; it < 2; it++) {
            int idx = tid + it * 1024;
            if (idx < mC) {
                unsigned long long key = sm.keys[idx];
                int bk = bucket_of((unsigned)(key >> 32));
                int base = suffix_from(sm, bk + 1);
                int end = min(base + sm.hist[bk], SORTN);
                int rank = base;
                for (int j = base; j < end; j++) rank += (sm.keys[j] > key);
                if (rank < PRE) sm.skeys[rank] = key;
            }
        }
    }
    __syncthreads();

    // ---- decode top-1000, gather boxes, block max ----
    {
        unsigned long long key = (tid < PRE) ? sm.skeys[tid] : 0ull;
        float sc = -1.0f;
        unsigned flat = 0u;
        if (tid < PRE && key != 0ull) {
            sc = __uint_as_float((unsigned)(key >> 32));
            flat = ~((unsigned)(key & 0xffffffffull));
        }
        unsigned a = flat / 80u;
        unsigned lbl = flat - a * 80u;
        if (a >= ANCH) { a = 0; lbl = 0; }
        const float* row = preds + ((size_t)b * ANCH + a) * ROW;
        float b0 = row[0], b1 = row[1], b2 = row[2], b3 = row[3];
        sm.rbx1[tid] = b0; sm.rby1[tid] = b1; sm.rbx2[tid] = b2; sm.rby2[tid] = b3;
        sm.ssc[tid] = sc;
        sm.slb[tid] = (int)lbl;
        if (tid < PRE) {
            float mx = fmaxf(fmaxf(b0, b1), fmaxf(b2, b3));
            atomicMax(&sm.smax, __float_as_int(mx));  // coords >= 0
        }
    }
    __syncthreads();

    // ---- class shift (bit-exact reference arithmetic) ----
    {
        float M = __int_as_float(sm.smax);
        float shb = __fadd_rn(M, 1.0f);
        float sh = __fmul_rn((float)sm.slb[tid], shb);
        float x1 = __fadd_rn(sm.rbx1[tid], sh);
        float y1 = __fadd_rn(sm.rby1[tid], sh);
        float x2 = __fadd_rn(sm.rbx2[tid], sh);
        float y2 = __fadd_rn(sm.rby2[tid], sh);
        sm.sx1[tid] = x1; sm.sy1[tid] = y1; sm.sx2[tid] = x2; sm.sy2[tid] = y2;
        sm.sar[tid] = __fmul_rn(fmaxf(__fsub_rn(x2, x1), 0.0f),
                                fmaxf(__fsub_rn(y2, y1), 0.0f));
    }

    // ---- stable per-class grouping: match_any + per-warp class counts ----
    int mylbl = (tid < PRE) ? sm.slb[tid] : -1;
    unsigned grpm = __match_any_sync(FULLM, mylbl);
    int wrank = __popc(grpm & ((1u << lane) - 1u));
    if (tid < PRE && wrank == 0)
        sm.wcnt[wid * NCLS + mylbl] = __popc(grpm);
    __syncthreads();
    if (tid < PRE) {
        int base = 0;
        for (int w = 0; w < wid; w++) base += sm.wcnt[w * NCLS + mylbl];
        int pos = base + wrank;
        if (pos < MAXK) sm.clist[mylbl * MAXK + pos] = tid;
    }
    __syncthreads();

    // ---- warp-parallel per-class greedy NMS (one warp per class) ----
    // Cross-class shifted IoU is exactly 0, so classes are independent.
    for (int c = wid; c < NCLS; c += 32) {
        int kc = __reduce_add_sync(FULLM, sm.wcnt[lane * NCLS + c]);
        kc = min(kc, MAXK);
        if (kc == 0) continue;
        int i1 = lane, i2 = lane + 32;
        int j1 = (i1 < kc) ? sm.clist[c * MAXK + i1] : 0;
        int j2 = (i2 < kc) ? sm.clist[c * MAXK + i2] : 0;
        float x1a = sm.sx1[j1], y1a = sm.sy1[j1];
        float x2a = sm.sx2[j1], y2a = sm.sy2[j1], ara = sm.sar[j1];
        float x1b = sm.sx1[j2], y1b = sm.sy1[j2];
        float x2b = sm.sx2[j2], y2b = sm.sy2[j2], arb = sm.sar[j2];
        unsigned m1 = __ballot_sync(FULLM, i1 < kc && sm.ssc[j1] > CONF_THRESH);
        unsigned m2 = __ballot_sync(FULLM, i2 < kc && sm.ssc[j2] > CONF_THRESH);
        unsigned long long keep =
            (unsigned long long)m1 | ((unsigned long long)m2 << 32);
        for (int ii = 0; ii < kc; ii++) {
            if (!((keep >> ii) & 1ull)) continue;  // keep is warp-uniform
            int src = ii & 31;
            bool hi = ii >= 32;
            float px1 = __shfl_sync(FULLM, hi ? x1b : x1a, src);
            float py1 = __shfl_sync(FULLM, hi ? y1b : y1a, src);
            float px2 = __shfl_sync(FULLM, hi ? x2b : x2a, src);
            float py2 = __shfl_sync(FULLM, hi ? y2b : y2a, src);
            float par = __shfl_sync(FULLM, hi ? arb : ara, src);
            // slot 1 (item index i1)
            float iw1 = fmaxf(__fsub_rn(fminf(px2, x2a), fmaxf(px1, x1a)), 0.0f);
            float ih1 = fmaxf(__fsub_rn(fminf(py2, y2a), fmaxf(py1, y1a)), 0.0f);
            float it1 = __fmul_rn(iw1, ih1);
            float dn1 = __fadd_rn(__fsub_rn(__fadd_rn(par, ara), it1), 1e-7f);
            bool s1 = (i1 > ii) && (i1 < kc) &&
                      (__fdiv_rn(it1, dn1) > NMS_THRESH);
            // slot 2 (item index i2)
            float iw2 = fmaxf(__fsub_rn(fminf(px2, x2b), fmaxf(px1, x1b)), 0.0f);
            float ih2 = fmaxf(__fsub_rn(fminf(py2, y2b), fmaxf(py1, y1b)), 0.0f);
            float it2 = __fmul_rn(iw2, ih2);
            float dn2 = __fadd_rn(__fsub_rn(__fadd_rn(par, arb), it2), 1e-7f);
            bool s2 = (i2 > ii) && (i2 < kc) &&
                      (__fdiv_rn(it2, dn2) > NMS_THRESH);
            unsigned b1 = __ballot_sync(FULLM, s1);
            unsigned b2 = __ballot_sync(FULLM, s2);
            keep &= ~((unsigned long long)b1 | ((unsigned long long)b2 << 32));
        }
        if (i1 < kc) sm.keepf[j1] = (int)((keep >> i1) & 1ull);
        if (i2 < kc) sm.keepf[j2] = (int)((keep >> i2) & 1ull);
    }
    __syncthreads();

    // ---- keep-flag prefix sum (warp shuffles) ----
    int myscan, total;
    {
        int p = sm.keepf[tid];
#pragma unroll
        for (int off = 1; off < 32; off <<= 1) {
            int t = __shfl_up_sync(FULLM, p, off);
            if (lane >= off) p += t;
        }
        if (lane == 31) sm.wscan[wid] = p;
        __syncthreads();
        if (wid == 0) {
            int w = sm.wscan[lane];
            __syncwarp();
#pragma unroll
            for (int off = 1; off < 32; off <<= 1) {
                int t = __shfl_up_sync(FULLM, w, off);
                if (lane >= off) w += t;
            }
            sm.wscan[lane] = w;
        }
        __syncthreads();
        int base = (wid > 0) ? sm.wscan[wid - 1] : 0;
        myscan = base + p;
        total = sm.wscan[31];
    }

    // ---- emit top-300 ----
    float* ob = out;                               // [16][300][4]
    float* os = out + (size_t)BATCH * MAXDET * 4;  // [16][300]
    float* ol = out + (size_t)BATCH * MAXDET * 5;  // [16][300] labels as f32

    if (tid < PRE && sm.keepf[tid]) {
        int m = myscan - 1;
        if (m < MAXDET) {
            float* p = ob + ((size_t)b * MAXDET + m) * 4;
            p[0] = sm.rbx1[tid]; p[1] = sm.rby1[tid];
            p[2] = sm.rbx2[tid]; p[3] = sm.rby2[tid];
            os[b * MAXDET + m] = sm.ssc[tid];
            ol[b * MAXDET + m] = (float)sm.slb[tid];
        }
    }
    for (int m = tid; m < MAXDET; m += 1024) {
        if (m >= total) {
            float* p = ob + ((size_t)b * MAXDET + m) * 4;
            p[0] = 0.0f; p[1] = 0.0f; p[2] = 0.0f; p[3] = 0.0f;
            os[b * MAXDET + m] = 0.0f;
            ol[b * MAXDET + m] = -1.0f;
        }
    }
}

extern "C" void kernel_launch(void* const* d_in, const int* in_sizes, int n_in,
                              void* d_out, int out_size) {
    (void)in_sizes; (void)n_in; (void)out_size;
    const float* preds = (const float*)d_in[0];
    float* out = (float*)d_out;

    cudaFuncSetAttribute(final_kernel,
                         cudaFuncAttributeMaxDynamicSharedMemorySize,
                         (int)sizeof(SMF));

    scan_kernel<<<dim3(ABLK, BATCH), 256>>>(preds);
    final_kernel<<<BATCH, 1024, sizeof(SMF)>>>(preds, out);
}

// round 6
// speedup vs baseline: 6.4180x; 1.0326x over previous
#include <cuda_runtime.h>

#define BATCH 16
#define ANCH 22743
#define ROW 85
#define NCLS 80
#define NSC (ANCH * NCLS)
#define ABLK 89            // ceil(ANCH / 256)
#define SEGW 1024          // candidate slots per scan block
#define PRE 1000
#define MAXDET 300
#define CONF_THRESH 0.2f
#define PRE_THRESH 0.9f
#define NMS_THRESH 0.45f
#define MAXK 64
#define NB 12288           // (1.0f bits - BOFF) >> 11
#define BOFF 0x3E000000u
#define GRP 12             // buckets per suffix-scan group (NB / 1024)
#define SORTN 2048
#define FULLM 0xffffffffu

// ---------------- device scratch (static; no allocations) ----------------
__device__ unsigned long long g_cand[BATCH][ABLK * SEGW];
__device__ float4 g_cbox[BATCH][ABLK * SEGW];
__device__ int g_bcnt[BATCH][ABLK];
__device__ int g_hist[BATCH][NB];    // zero at load; final re-zeroes each run
__device__ int g_ntot[BATCH];
__device__ int g_over[BATCH];

struct SMF {
    unsigned long long keys[SORTN];   // bucket-grouped candidates >= cutoff
    unsigned long long skeys[1024];   // rank-ordered top-1000 keys
    int aux[SORTN];                   // source slot (fast) / flat (slow)
    int hist[NB];
    int bpos[NB];                     // per-bucket scatter counters
    int rsum[1024];                   // per-GRP-bucket-group inclusive suffix
    int wred[33];
    int wcnt[32 * NCLS];              // per-warp per-class counts
    float rbx1[1024], rby1[1024], rbx2[1024], rby2[1024];
    float sx1[1024], sy1[1024], sx2[1024], sy2[1024], sar[1024];
    float ssc[1024];
    int slb[1024];
    int clist[NCLS * MAXK];
    int keepf[1024];
    int wscan[33];
    int n_tot, over, cstar, mcnt, smax;
};

__device__ __forceinline__ int bucket_of(unsigned sb) {
    return min((int)((sb - BOFF) >> 11), NB - 1);
}

// Scan: conf>0.9 prefilter, warp-cooperative scoring, emit s>0.9 candidates
// (key + box + global histogram + totals). Shared counter -> no reset pass.
__global__ void scan_kernel(const float* __restrict__ preds) {
    __shared__ int s_cnt;
    int b = blockIdx.y;
    int c = blockIdx.x;
    if (threadIdx.x == 0) s_cnt = 0;
    __syncthreads();
    int a0 = c * 256 + threadIdx.x;
    int lane = threadIdx.x & 31;
    bool inb = a0 < ANCH;
    float conf0 = inb ? preds[((size_t)b * ANCH + a0) * ROW + 4] : 0.0f;
    unsigned m = __ballot_sync(FULLM, inb && (conf0 > PRE_THRESH));
    unsigned long long* seg = g_cand[b] + c * SEGW;
    float4* segb = g_cbox[b] + c * SEGW;
    while (m) {
        int src = __ffs(m) - 1;
        m &= m - 1;
        int a = __shfl_sync(FULLM, a0, src);
        float conf = __shfl_sync(FULLM, conf0, src);
        const float* row = preds + ((size_t)b * ANCH + a) * ROW;
#pragma unroll
        for (int part = 0; part < 3; part++) {
            int k = part * 32 + lane;
            float p = (k < NCLS) ? row[5 + k] : 0.0f;
            float s = __fmul_rn(p, conf);
            bool pr = (k < NCLS) && (s > PRE_THRESH);
            unsigned mm = __ballot_sync(FULLM, pr);
            if (pr) {
                unsigned sb = __float_as_uint(s);
                atomicAdd(&g_hist[b][bucket_of(sb)], 1);
                int leader = __ffs(mm) - 1;
                int rank = __popc(mm & ((1u << lane) - 1u));
                int basep;
                if (lane == leader) basep = atomicAdd(&s_cnt, __popc(mm));
                basep = __shfl_sync(mm, basep, leader);
                int pos = basep + rank;
                if (pos < SEGW) {
                    unsigned flat = (unsigned)a * 80u + (unsigned)k;
                    seg[pos] = ((unsigned long long)sb << 32) |
                               (unsigned long long)(~flat);
                    segb[pos] = make_float4(row[0], row[1], row[2], row[3]);
                }
            }
        }
    }
    __syncthreads();
    if (threadIdx.x == 0) {
        g_bcnt[b][c] = s_cnt;  // true (unsaturated) count
        atomicAdd(&g_ntot[b], s_cnt);
        if (s_cnt > SEGW) atomicOr(&g_over[b], 1);
    }
}

// Count of histogram items in buckets >= bk (bk in [0, NB])
__device__ __forceinline__ int suffix_from(const SMF& sm, int bk) {
    if (bk >= NB) return 0;
    int g = bk / GRP;
    int s = (g + 1 < 1024) ? sm.rsum[g + 1] : 0;
    int e = g * GRP + GRP;
    for (int q = bk; q < e; q++) s += sm.hist[q];
    return s;
}

__global__ void __launch_bounds__(1024, 1)
final_kernel(const float* __restrict__ preds, float* __restrict__ out) {
    extern __shared__ char smc[];
    SMF& sm = *(SMF*)smc;
    int b = blockIdx.x;
    int tid = threadIdx.x;
    int lane = tid & 31;
    int wid = tid >> 5;

    // ---- init; load global hist into smem and re-zero it for next run ----
    for (int i = tid; i < SORTN; i += 1024) sm.keys[i] = 0ull;
    sm.skeys[tid] = 0ull;
#pragma unroll
    for (int q = 0; q < NB / 1024; q++) {
        int i = tid + q * 1024;
        int v = g_hist[b][i];
        sm.hist[i] = v;
        g_hist[b][i] = 0;
        sm.bpos[i] = 0;
    }
    for (int i = tid; i < 32 * NCLS; i += 1024) sm.wcnt[i] = 0;
    sm.keepf[tid] = 0;
    if (tid == 0) {
        sm.n_tot = g_ntot[b];
        sm.over = g_over[b];
        g_ntot[b] = 0;
        g_over[b] = 0;
        sm.cstar = NB;
        sm.smax = 0;
    }
    __syncthreads();
    bool slow = (sm.n_tot < PRE) || sm.over;

    // ---- slow path only: recompute full histogram over scores > 0.2 ----
    if (slow) {
#pragma unroll
        for (int q = 0; q < NB / 1024; q++) sm.hist[tid + q * 1024] = 0;
        __syncthreads();
        const float* bp = preds + (size_t)b * ANCH * ROW;
        for (int i = tid; i < NSC; i += 1024) {
            int a = i / 80, k = i - a * 80;
            float s = __fmul_rn(bp[(size_t)a * ROW + 5 + k], bp[(size_t)a * ROW + 4]);
            if (s > CONF_THRESH)
                atomicAdd(&sm.hist[bucket_of(__float_as_uint(s))], 1);
        }
        __syncthreads();
    }

    // ---- suffix sums over GRP-bucket groups (warp shuffles) ----
    {
        int v = 0;
#pragma unroll
        for (int q = 0; q < GRP; q++) v += sm.hist[tid * GRP + q];
#pragma unroll
        for (int off = 1; off < 32; off <<= 1) {
            int t = __shfl_down_sync(FULLM, v, off);
            if (lane + off < 32) v += t;
        }
        if (lane == 0) sm.wred[wid] = v;
        __syncthreads();
        if (wid == 0) {
            int w = sm.wred[lane];
            __syncwarp();
#pragma unroll
            for (int off = 1; off < 32; off <<= 1) {
                int t = __shfl_down_sync(FULLM, w, off);
                if (lane + off < 32) w += t;
            }
            sm.wred[lane] = w;  // inclusive suffix over warp totals
        }
        __syncthreads();
        int suffix = v + ((wid < 31) ? sm.wred[wid + 1] : 0);
        sm.rsum[tid] = suffix;
    }
    __syncthreads();

    int t_target = min(PRE, sm.rsum[0]);

    // ---- cutoff bucket: smallest bk with suffix count >= t_target ----
    if (t_target > 0 && sm.rsum[tid] >= t_target &&
        (tid == 1023 || sm.rsum[tid + 1] < t_target)) {
        int acc = (tid < 1023) ? sm.rsum[tid + 1] : 0;
        for (int bk = tid * GRP + GRP - 1; bk >= tid * GRP; bk--) {
            acc += sm.hist[bk];
            if (acc >= t_target) { sm.cstar = bk; break; }
        }
    }
    __syncthreads();
    int cstar = sm.cstar;
    if (tid == 0) sm.mcnt = suffix_from(sm, cstar);

    // ---- compact: scatter each passing key into its bucket's region ----
    if (!slow) {
        for (int c = wid; c < ABLK; c += 32) {
            int cnt = g_bcnt[b][c];
            const unsigned long long* seg = g_cand[b] + c * SEGW;
            for (int i = lane; i < cnt; i += 32) {
                unsigned long long key = seg[i];
                int bk = bucket_of((unsigned)(key >> 32));
                if (bk >= cstar) {
                    int slot = atomicAdd(&sm.bpos[bk], 1);
                    int pos = suffix_from(sm, bk + 1) + slot;
                    if (pos < SORTN) {
                        sm.keys[pos] = key;
                        sm.aux[pos] = c * SEGW + i;
                    }
                }
            }
        }
    } else {
        const float* bp = preds + (size_t)b * ANCH * ROW;
        for (int i = tid; i < NSC; i += 1024) {
            int a = i / 80, k = i - a * 80;
            float s = __fmul_rn(bp[(size_t)a * ROW + 5 + k], bp[(size_t)a * ROW + 4]);
            if (s > CONF_THRESH) {
                int bk = bucket_of(__float_as_uint(s));
                if (bk >= cstar) {
                    int slot = atomicAdd(&sm.bpos[bk], 1);
                    int pos = suffix_from(sm, bk + 1) + slot;
                    if (pos < SORTN) {
                        sm.keys[pos] =
                            ((unsigned long long)__float_as_uint(s) << 32) |
                            (unsigned long long)(~(unsigned)i);
                        sm.aux[pos] = i;  // flat index in slow path
                    }
                }
            }
        }
    }
    __syncthreads();

    // ---- exact rank (bucket base + within-bucket count); fill boxes ----
    {
        int mC = min(sm.mcnt, SORTN);
#pragma unroll
        for (int it = 0; it < 2; it++) {
            int idx = tid + it * 1024;
            if (idx < mC) {
                unsigned long long key = sm.keys[idx];
                int bk = bucket_of((unsigned)(key >> 32));
                int base = suffix_from(sm, bk + 1);
                int end = min(base + sm.hist[bk], SORTN);
                int rank = base;
                for (int j = base; j < end; j++) rank += (sm.keys[j] > key);
                if (rank < PRE) {
                    sm.skeys[rank] = key;
                    float4 bx;
                    if (!slow) {
                        bx = g_cbox[b][sm.aux[idx]];
                    } else {
                        unsigned flat = (unsigned)sm.aux[idx];
                        const float* row =
                            preds + ((size_t)b * ANCH + flat / 80u) * ROW;
                        bx = make_float4(row[0], row[1], row[2], row[3]);
                    }
                    sm.rbx1[rank] = bx.x; sm.rby1[rank] = bx.y;
                    sm.rbx2[rank] = bx.z; sm.rby2[rank] = bx.w;
                }
            }
        }
    }
    __syncthreads();

    // ---- decode top-1000: score/label, block max over boxes ----
    {
        unsigned long long key = (tid < PRE) ? sm.skeys[tid] : 0ull;
        float sc = -1.0f;
        unsigned flat = 0u;
        if (tid < PRE && key != 0ull) {
            sc = __uint_as_float((unsigned)(key >> 32));
            flat = ~((unsigned)(key & 0xffffffffull));
        }
        unsigned lbl = flat - (flat / 80u) * 80u;
        sm.ssc[tid] = sc;
        sm.slb[tid] = (int)lbl;
        if (tid < PRE && key != 0ull) {
            float mx = fmaxf(fmaxf(sm.rbx1[tid], sm.rby1[tid]),
                             fmaxf(sm.rbx2[tid], sm.rby2[tid]));
            atomicMax(&sm.smax, __float_as_int(mx));  // coords >= 0
        }
    }
    __syncthreads();

    // ---- class shift (bit-exact reference arithmetic) ----
    {
        float M = __int_as_float(sm.smax);
        float shb = __fadd_rn(M, 1.0f);
        float sh = __fmul_rn((float)sm.slb[tid], shb);
        float x1 = __fadd_rn(sm.rbx1[tid], sh);
        float y1 = __fadd_rn(sm.rby1[tid], sh);
        float x2 = __fadd_rn(sm.rbx2[tid], sh);
        float y2 = __fadd_rn(sm.rby2[tid], sh);
        sm.sx1[tid] = x1; sm.sy1[tid] = y1; sm.sx2[tid] = x2; sm.sy2[tid] = y2;
        sm.sar[tid] = __fmul_rn(fmaxf(__fsub_rn(x2, x1), 0.0f),
                                fmaxf(__fsub_rn(y2, y1), 0.0f));
    }

    // ---- stable per-class grouping: match_any + per-warp class counts ----
    int mylbl = (tid < PRE) ? sm.slb[tid] : -1;
    unsigned grpm = __match_any_sync(FULLM, mylbl);
    int wrank = __popc(grpm & ((1u << lane) - 1u));
    if (tid < PRE && wrank == 0)
        sm.wcnt[wid * NCLS + mylbl] = __popc(grpm);
    __syncthreads();
    if (tid < PRE) {
        int base = 0;
        for (int w = 0; w < wid; w++) base += sm.wcnt[w * NCLS + mylbl];
        int pos = base + wrank;
        if (pos < MAXK) sm.clist[mylbl * MAXK + pos] = tid;
    }
    __syncthreads();

    // ---- warp-parallel per-class greedy NMS (one warp per class) ----
    for (int c = wid; c < NCLS; c += 32) {
        int kc = __reduce_add_sync(FULLM, sm.wcnt[lane * NCLS + c]);
        kc = min(kc, MAXK);
        if (kc == 0) continue;
        if (kc <= 32) {
            // fast path: one item per lane
            int j1 = (lane < kc) ? sm.clist[c * MAXK + lane] : 0;
            float x1a = sm.sx1[j1], y1a = sm.sy1[j1];
            float x2a = sm.sx2[j1], y2a = sm.sy2[j1], ara = sm.sar[j1];
            unsigned keep =
                __ballot_sync(FULLM, lane < kc && sm.ssc[j1] > CONF_THRESH);
            for (int ii = 0; ii < kc; ii++) {
                if (!((keep >> ii) & 1u)) continue;  // warp-uniform
                float px1 = __shfl_sync(FULLM, x1a, ii);
                float py1 = __shfl_sync(FULLM, y1a, ii);
                float px2 = __shfl_sync(FULLM, x2a, ii);
                float py2 = __shfl_sync(FULLM, y2a, ii);
                float par = __shfl_sync(FULLM, ara, ii);
                float iw = fmaxf(__fsub_rn(fminf(px2, x2a), fmaxf(px1, x1a)), 0.0f);
                float ih = fmaxf(__fsub_rn(fminf(py2, y2a), fmaxf(py1, y1a)), 0.0f);
                float inter = __fmul_rn(iw, ih);
                float den = __fadd_rn(__fsub_rn(__fadd_rn(par, ara), inter), 1e-7f);
                bool s1 = (lane > ii) && (lane < kc) &&
                          (__fdiv_rn(inter, den) > NMS_THRESH);
                keep &= ~__ballot_sync(FULLM, s1);
            }
            if (lane < kc) sm.keepf[j1] = (int)((keep >> lane) & 1u);
        } else {
            // rare path: two items per lane
            int i1 = lane, i2 = lane + 32;
            int j1 = sm.clist[c * MAXK + i1];
            int j2 = (i2 < kc) ? sm.clist[c * MAXK + i2] : 0;
            float x1a = sm.sx1[j1], y1a = sm.sy1[j1];
            float x2a = sm.sx2[j1], y2a = sm.sy2[j1], ara = sm.sar[j1];
            float x1b = sm.sx1[j2], y1b = sm.sy1[j2];
            float x2b = sm.sx2[j2], y2b = sm.sy2[j2], arb = sm.sar[j2];
            unsigned m1 = __ballot_sync(FULLM, sm.ssc[j1] > CONF_THRESH);
            unsigned m2 =
                __ballot_sync(FULLM, i2 < kc && sm.ssc[j2] > CONF_THRESH);
            unsigned long long keep =
                (unsigned long long)m1 | ((unsigned long long)m2 << 32);
            for (int ii = 0; ii < kc; ii++) {
                if (!((keep >> ii) & 1ull)) continue;
                int src = ii & 31;
                bool hi = ii >= 32;
                float px1 = __shfl_sync(FULLM, hi ? x1b : x1a, src);
                float py1 = __shfl_sync(FULLM, hi ? y1b : y1a, src);
                float px2 = __shfl_sync(FULLM, hi ? x2b : x2a, src);
                float py2 = __shfl_sync(FULLM, hi ? y2b : y2a, src);
                float par = __shfl_sync(FULLM, hi ? arb : ara, src);
                float iw1 = fmaxf(__fsub_rn(fminf(px2, x2a), fmaxf(px1, x1a)), 0.0f);
                float ih1 = fmaxf(__fsub_rn(fminf(py2, y2a), fmaxf(py1, y1a)), 0.0f);
                float it1 = __fmul_rn(iw1, ih1);
                float dn1 = __fadd_rn(__fsub_rn(__fadd_rn(par, ara), it1), 1e-7f);
                bool s1 = (i1 > ii) && (__fdiv_rn(it1, dn1) > NMS_THRESH);
                float iw2 = fmaxf(__fsub_rn(fminf(px2, x2b), fmaxf(px1, x1b)), 0.0f);
                float ih2 = fmaxf(__fsub_rn(fminf(py2, y2b), fmaxf(py1, y1b)), 0.0f);
                float it2 = __fmul_rn(iw2, ih2);
                float dn2 = __fadd_rn(__fsub_rn(__fadd_rn(par, arb), it2), 1e-7f);
                bool s2 = (i2 > ii) && (i2 < kc) &&
                          (__fdiv_rn(it2, dn2) > NMS_THRESH);
                unsigned b1 = __ballot_sync(FULLM, s1);
                unsigned b2 = __ballot_sync(FULLM, s2);
                keep &= ~((unsigned long long)b1 |
                          ((unsigned long long)b2 << 32));
            }
            sm.keepf[j1] = (int)((keep >> i1) & 1ull);
            if (i2 < kc) sm.keepf[j2] = (int)((keep >> i2) & 1ull);
        }
    }
    __syncthreads();

    // ---- keep-flag prefix sum (warp shuffles) ----
    int myscan, total;
    {
        int p = sm.keepf[tid];
#pragma unroll
        for (int off = 1; off < 32; off <<= 1) {
            int t = __shfl_up_sync(FULLM, p, off);
            if (lane >= off) p += t;
        }
        if (lane == 31) sm.wscan[wid] = p;
        __syncthreads();
        if (wid == 0) {
            int w = sm.wscan[lane];
            __syncwarp();
#pragma unroll
            for (int off = 1; off < 32; off <<= 1) {
                int t = __shfl_up_sync(FULLM, w, off);
                if (lane >= off) w += t;
            }
            sm.wscan[lane] = w;
        }
        __syncthreads();
        int base = (wid > 0) ? sm.wscan[wid - 1] : 0;
        myscan = base + p;
        total = sm.wscan[31];
    }

    // ---- emit top-300 ----
    float* ob = out;                               // [16][300][4]
    float* os = out + (size_t)BATCH * MAXDET * 4;  // [16][300]
    float* ol = out + (size_t)BATCH * MAXDET * 5;  // [16][300] labels as f32

    if (tid < PRE && sm.keepf[tid]) {
        int m = myscan - 1;
        if (m < MAXDET) {
            float* p = ob + ((size_t)b * MAXDET + m) * 4;
            p[0] = sm.rbx1[tid]; p[1] = sm.rby1[tid];
            p[2] = sm.rbx2[tid]; p[3] = sm.rby2[tid];
            os[b * MAXDET + m] = sm.ssc[tid];
            ol[b * MAXDET + m] = (float)sm.slb[tid];
        }
    }
    for (int m = tid; m < MAXDET; m += 1024) {
        if (m >= total) {
            float* p = ob + ((size_t)b * MAXDET + m) * 4;
            p[0] = 0.0f; p[1] = 0.0f; p[2] = 0.0f; p[3] = 0.0f;
            os[b * MAXDET + m] = 0.0f;
            ol[b * MAXDET + m] = -1.0f;
        }
    }
}

extern "C" void kernel_launch(void* const* d_in, const int* in_sizes, int n_in,
                              void* d_out, int out_size) {
    (void)in_sizes; (void)n_in; (void)out_size;
    const float* preds = (const float*)d_in[0];
    float* out = (float*)d_out;

    cudaFuncSetAttribute(final_kernel,
                         cudaFuncAttributeMaxDynamicSharedMemorySize,
                         (int)sizeof(SMF));

    scan_kernel<<<dim3(ABLK, BATCH), 256>>>(preds);
    final_kernel<<<BATCH, 1024, sizeof(SMF)>>>(preds, out);
}